// round 1
// baseline (speedup 1.0000x reference)
#include <cuda_runtime.h>
#include <math.h>

#define NN 100000
#define EE 1600000

// ---------------- scratch (static device globals; no allocs allowed) ----------
__device__ float g_h1[NN * 256];
__device__ float g_h2[NN * 256];
__device__ float g_p64[NN * 64];
__device__ float g_dinv[NN];
__device__ int   g_deg[NN];
__device__ int   g_rowptr[NN + 1];
__device__ int   g_cursor[NN];
__device__ int   g_csr_src[EE];
__device__ float g_csr_coef[EE];
__device__ int   g_blksum[128];
__device__ int   g_blkoff[128];
__device__ int   g_is64;
__device__ float g_Wp[4 * 256 * 64];   // padded projection weights (cols 40..63 zero)

// ---------------- edge index dtype handling ----------------------------------
__device__ __forceinline__ int edge_at(const void* ei, long long idx) {
    if (g_is64) return (int)((const long long*)ei)[idx];
    return ((const int*)ei)[idx];
}

__global__ void detect_kernel(const int* ei32) {
    if (threadIdx.x == 0) {
        int nz = 0;
        for (int i = 0; i < 64; i++) nz |= ei32[2 * i + 1];
        // int64 little-endian: odd 32-bit words are hi-words == 0 (ids < 2^31)
        g_is64 = (nz == 0) ? 1 : 0;
    }
}

// ---------------- degree / dinv ----------------------------------------------
__global__ void zero_deg_kernel() {
    int i = blockIdx.x * blockDim.x + threadIdx.x;
    if (i < NN) g_deg[i] = 0;
}

__global__ void count_kernel(const void* ei, int E) {
    int e = blockIdx.x * blockDim.x + threadIdx.x;
    if (e >= E) return;
    int d = edge_at(ei, (long long)E + e);
    atomicAdd(&g_deg[d], 1);
}

__global__ void dinv_kernel() {
    int i = blockIdx.x * blockDim.x + threadIdx.x;
    if (i < NN) g_dinv[i] = rsqrtf((float)g_deg[i] + 1.0f);
}

// ---------------- exclusive scan (3 kernels) ----------------------------------
__global__ void scan1_kernel() {
    __shared__ int s[1024];
    int t = threadIdx.x;
    int idx = blockIdx.x * 1024 + t;
    int v = (idx < NN) ? g_deg[idx] : 0;
    s[t] = v;
    __syncthreads();
    for (int o = 1; o < 1024; o <<= 1) {
        int x = (t >= o) ? s[t - o] : 0;
        __syncthreads();
        s[t] += x;
        __syncthreads();
    }
    if (idx < NN) g_rowptr[idx] = s[t] - v;   // block-local exclusive
    if (t == 1023) g_blksum[blockIdx.x] = s[t];
}

__global__ void scan2_kernel(int nb) {
    if (threadIdx.x == 0 && blockIdx.x == 0) {
        int running = 0;
        for (int b = 0; b < nb; b++) {
            g_blkoff[b] = running;
            running += g_blksum[b];
        }
        g_rowptr[NN] = running;
    }
}

__global__ void scan3_kernel() {
    int i = blockIdx.x * blockDim.x + threadIdx.x;
    if (i < NN) {
        int r = g_rowptr[i] + g_blkoff[i >> 10];
        g_rowptr[i] = r;
        g_cursor[i] = r;
    }
}

__global__ void fill_kernel(const void* ei, int E) {
    int e = blockIdx.x * blockDim.x + threadIdx.x;
    if (e >= E) return;
    int s = edge_at(ei, e);
    int d = edge_at(ei, (long long)E + e);
    int pos = atomicAdd(&g_cursor[d], 1);
    g_csr_src[pos] = s;
    g_csr_coef[pos] = g_dinv[s] * g_dinv[d];
}

// ---------------- aggregation: warp per node, atomic-free gather --------------
template <int D>
__global__ void agg_kernel(const float* __restrict__ h, float* __restrict__ out) {
    const int F4 = D / 4;
    const int VP = F4 / 32;     // float4 per lane
    int warp = (blockIdx.x * blockDim.x + threadIdx.x) >> 5;
    int lane = threadIdx.x & 31;
    if (warp >= NN) return;
    const float4* hv = (const float4*)h;
    float dinv = g_dinv[warp];
    float c0 = dinv * dinv;
    float4 acc[VP];
#pragma unroll
    for (int i = 0; i < VP; i++) {
        float4 x = hv[warp * F4 + lane + 32 * i];
        acc[i] = make_float4(x.x * c0, x.y * c0, x.z * c0, x.w * c0);
    }
    int beg = g_rowptr[warp], end = g_rowptr[warp + 1];
    int j = beg;
    for (; j + 1 < end; j += 2) {
        int   sA = g_csr_src[j],     sB = g_csr_src[j + 1];
        float cA = g_csr_coef[j],    cB = g_csr_coef[j + 1];
        float4 vA[VP], vB[VP];
#pragma unroll
        for (int i = 0; i < VP; i++) vA[i] = __ldg(&hv[sA * F4 + lane + 32 * i]);
#pragma unroll
        for (int i = 0; i < VP; i++) vB[i] = __ldg(&hv[sB * F4 + lane + 32 * i]);
#pragma unroll
        for (int i = 0; i < VP; i++) {
            acc[i].x += cA * vA[i].x + cB * vB[i].x;
            acc[i].y += cA * vA[i].y + cB * vB[i].y;
            acc[i].z += cA * vA[i].z + cB * vB[i].z;
            acc[i].w += cA * vA[i].w + cB * vB[i].w;
        }
    }
    if (j < end) {
        int s = g_csr_src[j];
        float c = g_csr_coef[j];
#pragma unroll
        for (int i = 0; i < VP; i++) {
            float4 v = __ldg(&hv[s * F4 + lane + 32 * i]);
            acc[i].x += c * v.x; acc[i].y += c * v.y;
            acc[i].z += c * v.z; acc[i].w += c * v.w;
        }
    }
    float4* ov = (float4*)out;
#pragma unroll
    for (int i = 0; i < VP; i++) ov[warp * F4 + lane + 32 * i] = acc[i];
}

// ---------------- pad projection weights to 64 cols ---------------------------
__global__ void pad_w_kernel(const float* __restrict__ W, float* __restrict__ Wp, int K) {
    int idx = blockIdx.x * blockDim.x + threadIdx.x;
    if (idx >= K * 64) return;
    int k = idx >> 6, j = idx & 63;
    Wp[idx] = (j < 40) ? W[k * 40 + j] : 0.0f;
}

// ---------------- tiled fp32 GEMM: C[N,M] = A[N,K] @ W[K,M] (+bias, relu) -----
template <int K, int M, bool BIAS_RELU>
__global__ void gemm_kernel(const float* __restrict__ A, const float* __restrict__ W,
                            const float* __restrict__ bias, float* __restrict__ C) {
    // BM=128, BN=64, BK=16; 256 threads; 8x4 per thread
    __shared__ __align__(16) float As[16][132];
    __shared__ __align__(16) float Bs[16][64];
    const int t  = threadIdx.x;
    const int tx = t % 16;        // 16 col groups * 4 cols
    const int ty = t / 16;        // 16 row groups * 8 rows
    const int bm = blockIdx.x * 128;
    const int bn = blockIdx.y * 64;

    float acc[8][4];
#pragma unroll
    for (int i = 0; i < 8; i++)
#pragma unroll
        for (int j = 0; j < 4; j++) acc[i][j] = 0.0f;

    for (int k0 = 0; k0 < K; k0 += 16) {
#pragma unroll
        for (int r = 0; r < 8; r++) {
            int i = t + r * 256;
            int m = i >> 4, kk = i & 15;
            int row = bm + m;
            As[kk][m] = (row < NN) ? A[(long long)row * K + k0 + kk] : 0.0f;
        }
#pragma unroll
        for (int r = 0; r < 4; r++) {
            int i = t + r * 256;
            int kk = i >> 6, n = i & 63;
            Bs[kk][n] = W[(k0 + kk) * M + bn + n];
        }
        __syncthreads();
#pragma unroll
        for (int kk = 0; kk < 16; kk++) {
            float4 a0 = *(const float4*)&As[kk][ty * 8];
            float4 a1 = *(const float4*)&As[kk][ty * 8 + 4];
            float4 b0 = *(const float4*)&Bs[kk][tx * 4];
            float a[8] = {a0.x, a0.y, a0.z, a0.w, a1.x, a1.y, a1.z, a1.w};
            float b[4] = {b0.x, b0.y, b0.z, b0.w};
#pragma unroll
            for (int i = 0; i < 8; i++)
#pragma unroll
                for (int j = 0; j < 4; j++) acc[i][j] += a[i] * b[j];
        }
        __syncthreads();
    }
#pragma unroll
    for (int i = 0; i < 8; i++) {
        int row = bm + ty * 8 + i;
        if (row < NN) {
#pragma unroll
            for (int j = 0; j < 4; j++) {
                float v = acc[i][j];
                int col = bn + tx * 4 + j;
                if (BIAS_RELU) { v += bias[col]; v = fmaxf(v, 0.0f); }
                C[(long long)row * M + col] = v;
            }
        }
    }
}

// ---------------- bias + log_softmax over 40 cols (8 threads/node) ------------
__global__ void softmax40_kernel(const float* __restrict__ P, const float* __restrict__ bias,
                                 float* __restrict__ out, int layer) {
    int gid = blockIdx.x * (blockDim.x >> 3) + (threadIdx.x >> 3);
    int t = threadIdx.x & 7;
    bool valid = gid < NN;
    float v[5];
#pragma unroll
    for (int i = 0; i < 5; i++)
        v[i] = valid ? (P[(long long)gid * 64 + t + 8 * i] + bias[t + 8 * i]) : 0.0f;
    float m = fmaxf(fmaxf(fmaxf(v[0], v[1]), fmaxf(v[2], v[3])), v[4]);
#pragma unroll
    for (int o = 1; o < 8; o <<= 1) m = fmaxf(m, __shfl_xor_sync(0xffffffffu, m, o));
    float s = 0.0f;
#pragma unroll
    for (int i = 0; i < 5; i++) s += expf(v[i] - m);
#pragma unroll
    for (int o = 1; o < 8; o <<= 1) s += __shfl_xor_sync(0xffffffffu, s, o);
    float lse = m + logf(s);
    if (valid) {
        float* op = out + (long long)gid * 160 + layer * 40;
#pragma unroll
        for (int i = 0; i < 5; i++) op[t + 8 * i] = v[i] - lse;
    }
}

// ---------------- last layer: aggregate in 40-dim + bias + log_softmax --------
__global__ void agg40_kernel(const float* __restrict__ P, const float* __restrict__ bias,
                             float* __restrict__ out) {
    int gid = blockIdx.x * (blockDim.x >> 3) + (threadIdx.x >> 3);
    int t = threadIdx.x & 7;
    bool valid = gid < NN;
    float v[5];
    int beg = 0, end = 0;
    if (valid) {
        float dinv = g_dinv[gid];
        float c0 = dinv * dinv;
#pragma unroll
        for (int i = 0; i < 5; i++) v[i] = P[(long long)gid * 64 + t + 8 * i] * c0;
        beg = g_rowptr[gid];
        end = g_rowptr[gid + 1];
    } else {
#pragma unroll
        for (int i = 0; i < 5; i++) v[i] = 0.0f;
    }
    for (int j = beg; j < end; j++) {
        int s = g_csr_src[j];
        float c = g_csr_coef[j];
#pragma unroll
        for (int i = 0; i < 5; i++) v[i] += c * __ldg(&P[(long long)s * 64 + t + 8 * i]);
    }
#pragma unroll
    for (int i = 0; i < 5; i++) v[i] += bias[t + 8 * i];
    float m = fmaxf(fmaxf(fmaxf(v[0], v[1]), fmaxf(v[2], v[3])), v[4]);
#pragma unroll
    for (int o = 1; o < 8; o <<= 1) m = fmaxf(m, __shfl_xor_sync(0xffffffffu, m, o));
    float s = 0.0f;
#pragma unroll
    for (int i = 0; i < 5; i++) s += expf(v[i] - m);
#pragma unroll
    for (int o = 1; o < 8; o <<= 1) s += __shfl_xor_sync(0xffffffffu, s, o);
    float lse = m + logf(s);
    if (valid) {
        float* op = out + (long long)gid * 160 + 3 * 40;
#pragma unroll
        for (int i = 0; i < 5; i++) op[t + 8 * i] = v[i] - lse;
    }
}

// ---------------- launch -------------------------------------------------------
extern "C" void kernel_launch(void* const* d_in, const int* in_sizes, int n_in,
                              void* d_out, int out_size) {
    const float* x   = (const float*)d_in[0];
    const void*  ei  = d_in[1];
    const float* Wc0 = (const float*)d_in[2];
    const float* bc0 = (const float*)d_in[3];
    const float* Wc1 = (const float*)d_in[4];
    const float* bc1 = (const float*)d_in[5];
    // d_in[6], d_in[7] (Wc2, bc2): dead — final Wc output is never used
    const float* We0 = (const float*)d_in[8];
    const float* be0 = (const float*)d_in[9];
    const float* We1 = (const float*)d_in[10];
    const float* be1 = (const float*)d_in[11];
    const float* We2 = (const float*)d_in[12];
    const float* be2 = (const float*)d_in[13];
    const float* We3 = (const float*)d_in[14];
    const float* be3 = (const float*)d_in[15];
    float* out = (float*)d_out;
    int E = in_sizes[1] / 2;

    float *h1, *h2, *p64, *wp;
    cudaGetSymbolAddress((void**)&h1,  g_h1);
    cudaGetSymbolAddress((void**)&h2,  g_h2);
    cudaGetSymbolAddress((void**)&p64, g_p64);
    cudaGetSymbolAddress((void**)&wp,  g_Wp);
    float* wp0 = wp;
    float* wp1 = wp + 1 * 256 * 64;
    float* wp2 = wp + 2 * 256 * 64;
    float* wp3 = wp + 3 * 256 * 64;

    int nb = (NN + 1023) / 1024;

    // graph preprocessing: degrees, dinv, CSR
    detect_kernel<<<1, 32>>>((const int*)ei);
    zero_deg_kernel<<<(NN + 255) / 256, 256>>>();
    count_kernel<<<(E + 255) / 256, 256>>>(ei, E);
    dinv_kernel<<<(NN + 255) / 256, 256>>>();
    scan1_kernel<<<nb, 1024>>>();
    scan2_kernel<<<1, 32>>>(nb);
    scan3_kernel<<<(NN + 255) / 256, 256>>>();
    fill_kernel<<<(E + 255) / 256, 256>>>(ei, E);

    // pad projection weights to 64 cols
    pad_w_kernel<<<(128 * 64 + 255) / 256, 256>>>(We0, wp0, 128);
    pad_w_kernel<<<(128 * 64 + 255) / 256, 256>>>(We1, wp1, 128);
    pad_w_kernel<<<(256 * 64 + 255) / 256, 256>>>(We2, wp2, 256);
    pad_w_kernel<<<(256 * 64 + 255) / 256, 256>>>(We3, wp3, 256);

    dim3 g1((NN + 127) / 128, 1);
    dim3 g4((NN + 127) / 128, 4);
    int  gs = (NN + 31) / 32;     // softmax/agg40 grid (32 nodes / 256-thr block)
    int  ga = (NN + 7) / 8;       // agg grid (8 warps / block)

    // layer 0: log_softmax(x @ We0 + be0)
    gemm_kernel<128, 64, false><<<g1, 256>>>(x, wp0, nullptr, p64);
    softmax40_kernel<<<gs, 256>>>(p64, be0, out, 0);

    // agg1 (d=128)
    agg_kernel<128><<<ga, 256>>>(x, h1);
    gemm_kernel<128, 64, false><<<g1, 256>>>(h1, wp1, nullptr, p64);
    softmax40_kernel<<<gs, 256>>>(p64, be1, out, 1);
    gemm_kernel<128, 256, true><<<g4, 256>>>(h1, Wc0, bc0, h2);

    // agg2 (d=256)
    agg_kernel<256><<<ga, 256>>>(h2, h1);
    gemm_kernel<256, 64, false><<<g1, 256>>>(h1, wp2, nullptr, p64);
    softmax40_kernel<<<gs, 256>>>(p64, be2, out, 2);
    gemm_kernel<256, 256, true><<<g4, 256>>>(h1, Wc1, bc1, h2);

    // layer 3: agg(h) @ We3 == agg(h @ We3)  -> aggregate in 40-dim (6.4x less traffic)
    gemm_kernel<256, 64, false><<<g1, 256>>>(h2, wp3, nullptr, p64);
    agg40_kernel<<<gs, 256>>>(p64, be3, out);
}

// round 2
// speedup vs baseline: 1.4415x; 1.4415x over previous
#include <cuda_runtime.h>
#include <math.h>

#define NN 100000
#define EE 1600000

// ---------------- scratch (static device globals; no allocs allowed) ----------
__device__ float g_h1[NN * 256];
__device__ float g_h2[NN * 256];
__device__ float g_p64[NN * 64];
__device__ float g_dinv[NN];
__device__ int   g_deg[NN];
__device__ int   g_rowptr[NN + 1];
__device__ int   g_cursor[NN];
__device__ int   g_csr_src[EE];
__device__ float g_csr_coef[EE];
__device__ int   g_blksum[128];
__device__ int   g_blkoff[128];
__device__ int   g_is64;
__device__ float g_Wp[4 * 256 * 64];   // padded projection weights (cols 40..63 zero)

// ---------------- edge index dtype handling ----------------------------------
__device__ __forceinline__ int edge_at(const void* ei, long long idx) {
    if (g_is64) return (int)((const long long*)ei)[idx];
    return ((const int*)ei)[idx];
}

__global__ void detect_kernel(const int* ei32) {
    if (threadIdx.x == 0) {
        int nz = 0;
        for (int i = 0; i < 64; i++) nz |= ei32[2 * i + 1];
        // int64 little-endian: odd 32-bit words are hi-words == 0 (ids < 2^31)
        g_is64 = (nz == 0) ? 1 : 0;
    }
}

// ---------------- degree / dinv ----------------------------------------------
__global__ void zero_deg_kernel() {
    int i = blockIdx.x * blockDim.x + threadIdx.x;
    if (i < NN) g_deg[i] = 0;
}

__global__ void count_kernel(const void* ei, int E) {
    int e = blockIdx.x * blockDim.x + threadIdx.x;
    if (e >= E) return;
    int d = edge_at(ei, (long long)E + e);
    atomicAdd(&g_deg[d], 1);
}

__global__ void dinv_kernel() {
    int i = blockIdx.x * blockDim.x + threadIdx.x;
    if (i < NN) g_dinv[i] = rsqrtf((float)g_deg[i] + 1.0f);
}

// ---------------- exclusive scan (3 kernels) ----------------------------------
__global__ void scan1_kernel() {
    __shared__ int s[1024];
    int t = threadIdx.x;
    int idx = blockIdx.x * 1024 + t;
    int v = (idx < NN) ? g_deg[idx] : 0;
    s[t] = v;
    __syncthreads();
    for (int o = 1; o < 1024; o <<= 1) {
        int x = (t >= o) ? s[t - o] : 0;
        __syncthreads();
        s[t] += x;
        __syncthreads();
    }
    if (idx < NN) g_rowptr[idx] = s[t] - v;   // block-local exclusive
    if (t == 1023) g_blksum[blockIdx.x] = s[t];
}

__global__ void scan2_kernel(int nb) {
    if (threadIdx.x == 0 && blockIdx.x == 0) {
        int running = 0;
        for (int b = 0; b < nb; b++) {
            g_blkoff[b] = running;
            running += g_blksum[b];
        }
        g_rowptr[NN] = running;
    }
}

__global__ void scan3_kernel() {
    int i = blockIdx.x * blockDim.x + threadIdx.x;
    if (i < NN) {
        int r = g_rowptr[i] + g_blkoff[i >> 10];
        g_rowptr[i] = r;
        g_cursor[i] = r;
    }
}

__global__ void fill_kernel(const void* ei, int E) {
    int e = blockIdx.x * blockDim.x + threadIdx.x;
    if (e >= E) return;
    int s = edge_at(ei, e);
    int d = edge_at(ei, (long long)E + e);
    int pos = atomicAdd(&g_cursor[d], 1);
    g_csr_src[pos] = s;
    g_csr_coef[pos] = g_dinv[s] * g_dinv[d];
}

// ---------------- aggregation: warp per node, atomic-free gather --------------
template <int D>
__global__ void agg_kernel(const float* __restrict__ h, float* __restrict__ out) {
    const int F4 = D / 4;
    const int VP = F4 / 32;     // float4 per lane
    int warp = (blockIdx.x * blockDim.x + threadIdx.x) >> 5;
    int lane = threadIdx.x & 31;
    if (warp >= NN) return;
    const float4* hv = (const float4*)h;
    float dinv = g_dinv[warp];
    float c0 = dinv * dinv;
    float4 acc[VP];
#pragma unroll
    for (int i = 0; i < VP; i++) {
        float4 x = hv[warp * F4 + lane + 32 * i];
        acc[i] = make_float4(x.x * c0, x.y * c0, x.z * c0, x.w * c0);
    }
    int beg = g_rowptr[warp], end = g_rowptr[warp + 1];
    int j = beg;
    for (; j + 1 < end; j += 2) {
        int   sA = g_csr_src[j],     sB = g_csr_src[j + 1];
        float cA = g_csr_coef[j],    cB = g_csr_coef[j + 1];
        float4 vA[VP], vB[VP];
#pragma unroll
        for (int i = 0; i < VP; i++) vA[i] = __ldg(&hv[sA * F4 + lane + 32 * i]);
#pragma unroll
        for (int i = 0; i < VP; i++) vB[i] = __ldg(&hv[sB * F4 + lane + 32 * i]);
#pragma unroll
        for (int i = 0; i < VP; i++) {
            acc[i].x += cA * vA[i].x + cB * vB[i].x;
            acc[i].y += cA * vA[i].y + cB * vB[i].y;
            acc[i].z += cA * vA[i].z + cB * vB[i].z;
            acc[i].w += cA * vA[i].w + cB * vB[i].w;
        }
    }
    if (j < end) {
        int s = g_csr_src[j];
        float c = g_csr_coef[j];
#pragma unroll
        for (int i = 0; i < VP; i++) {
            float4 v = __ldg(&hv[s * F4 + lane + 32 * i]);
            acc[i].x += c * v.x; acc[i].y += c * v.y;
            acc[i].z += c * v.z; acc[i].w += c * v.w;
        }
    }
    float4* ov = (float4*)out;
#pragma unroll
    for (int i = 0; i < VP; i++) ov[warp * F4 + lane + 32 * i] = acc[i];
}

// ---------------- pad projection weights to 64 cols ---------------------------
__global__ void pad_w_kernel(const float* __restrict__ W, float* __restrict__ Wp, int K) {
    int idx = blockIdx.x * blockDim.x + threadIdx.x;
    if (idx >= K * 64) return;
    int k = idx >> 6, j = idx & 63;
    Wp[idx] = (j < 40) ? W[k * 40 + j] : 0.0f;
}

// ---------------- TF32 tensor-core GEMM ---------------------------------------
__device__ __forceinline__ unsigned f2tf32(float f) {
    unsigned u;
    asm("cvt.rna.tf32.f32 %0, %1;" : "=r"(u) : "f"(f));
    return u;
}

__device__ __forceinline__ void mma_tf32(float* c, const unsigned* a, const unsigned* b) {
    asm volatile(
        "mma.sync.aligned.m16n8k8.row.col.f32.tf32.tf32.f32 "
        "{%0,%1,%2,%3}, {%4,%5,%6,%7}, {%8,%9}, {%0,%1,%2,%3};"
        : "+f"(c[0]), "+f"(c[1]), "+f"(c[2]), "+f"(c[3])
        : "r"(a[0]), "r"(a[1]), "r"(a[2]), "r"(a[3]), "r"(b[0]), "r"(b[1]));
}

// C[N,M] = A[N,K] @ W[K,M] (+bias,relu). BM=128, BN=64, BK=32, 256 threads.
// 8 warps: 4 along M x 2 along N; per warp 32x32 = 2x4 m16n8k8 tiles.
template <int K, int M, bool BIAS_RELU>
__global__ void __launch_bounds__(256)
mma_gemm_kernel(const float* __restrict__ A, const float* __restrict__ W,
                const float* __restrict__ bias, float* __restrict__ C) {
    const int BK = 32;
    __shared__ __align__(16) unsigned As[128][BK + 4];   // stride 36
    __shared__ __align__(16) unsigned Bs[BK][64 + 4];    // stride 68
    const int t = threadIdx.x;
    const int lane = t & 31;
    const int warp = t >> 5;
    const int wm = warp & 3;           // 0..3 -> 32-row slab
    const int wn = warp >> 2;          // 0..1 -> 32-col slab
    const int bm = blockIdx.x * 128;
    const int bn = blockIdx.y * 64;

    float acc[2][4][4];
#pragma unroll
    for (int mi = 0; mi < 2; mi++)
#pragma unroll
        for (int ni = 0; ni < 4; ni++)
#pragma unroll
            for (int r = 0; r < 4; r++) acc[mi][ni][r] = 0.0f;

    for (int k0 = 0; k0 < K; k0 += BK) {
        // stage A tile (128 x 32) with tf32 conversion
#pragma unroll
        for (int r = 0; r < 4; r++) {
            int idx = t + r * 256;          // 1024 float4 slots
            int row = idx >> 3;             // 8 float4 per row
            int c4  = idx & 7;
            float4 v = make_float4(0.f, 0.f, 0.f, 0.f);
            if (bm + row < NN)
                v = *(const float4*)&A[(long long)(bm + row) * K + k0 + c4 * 4];
            uint4 u;
            u.x = f2tf32(v.x); u.y = f2tf32(v.y); u.z = f2tf32(v.z); u.w = f2tf32(v.w);
            *(uint4*)&As[row][c4 * 4] = u;
        }
        // stage B tile (32 x 64)
#pragma unroll
        for (int r = 0; r < 2; r++) {
            int idx = t + r * 256;          // 512 float4 slots
            int kk = idx >> 4;              // 16 float4 per row
            int c4 = idx & 15;
            float4 v = *(const float4*)&W[(long long)(k0 + kk) * M + bn + c4 * 4];
            uint4 u;
            u.x = f2tf32(v.x); u.y = f2tf32(v.y); u.z = f2tf32(v.z); u.w = f2tf32(v.w);
            *(uint4*)&Bs[kk][c4 * 4] = u;
        }
        __syncthreads();
#pragma unroll
        for (int ks = 0; ks < BK / 8; ks++) {
            unsigned a[2][4], b[4][2];
            const int ar = wm * 32 + (lane >> 2);
            const int ac = ks * 8 + (lane & 3);
#pragma unroll
            for (int mi = 0; mi < 2; mi++) {
                a[mi][0] = As[ar + mi * 16][ac];
                a[mi][1] = As[ar + mi * 16 + 8][ac];
                a[mi][2] = As[ar + mi * 16][ac + 4];
                a[mi][3] = As[ar + mi * 16 + 8][ac + 4];
            }
            const int br = ks * 8 + (lane & 3);
            const int bc = wn * 32 + (lane >> 2);
#pragma unroll
            for (int ni = 0; ni < 4; ni++) {
                b[ni][0] = Bs[br][bc + ni * 8];
                b[ni][1] = Bs[br + 4][bc + ni * 8];
            }
#pragma unroll
            for (int mi = 0; mi < 2; mi++)
#pragma unroll
                for (int ni = 0; ni < 4; ni++)
                    mma_tf32(acc[mi][ni], a[mi], b[ni]);
        }
        __syncthreads();
    }

    // epilogue
#pragma unroll
    for (int mi = 0; mi < 2; mi++) {
#pragma unroll
        for (int ni = 0; ni < 4; ni++) {
            int col = bn + wn * 32 + ni * 8 + 2 * (lane & 3);
            float bv0 = 0.f, bv1 = 0.f;
            if (BIAS_RELU) { bv0 = bias[col]; bv1 = bias[col + 1]; }
#pragma unroll
            for (int h = 0; h < 2; h++) {
                int row = bm + wm * 32 + mi * 16 + (lane >> 2) + h * 8;
                if (row < NN) {
                    float v0 = acc[mi][ni][2 * h];
                    float v1 = acc[mi][ni][2 * h + 1];
                    if (BIAS_RELU) {
                        v0 = fmaxf(v0 + bv0, 0.0f);
                        v1 = fmaxf(v1 + bv1, 0.0f);
                    }
                    *(float2*)&C[(long long)row * M + col] = make_float2(v0, v1);
                }
            }
        }
    }
}

// ---------------- bias + log_softmax over 40 cols (8 threads/node) ------------
__global__ void softmax40_kernel(const float* __restrict__ P, const float* __restrict__ bias,
                                 float* __restrict__ out, int layer) {
    int gid = blockIdx.x * (blockDim.x >> 3) + (threadIdx.x >> 3);
    int t = threadIdx.x & 7;
    bool valid = gid < NN;
    float v[5];
#pragma unroll
    for (int i = 0; i < 5; i++)
        v[i] = valid ? (P[(long long)gid * 64 + t + 8 * i] + bias[t + 8 * i]) : 0.0f;
    float m = fmaxf(fmaxf(fmaxf(v[0], v[1]), fmaxf(v[2], v[3])), v[4]);
#pragma unroll
    for (int o = 1; o < 8; o <<= 1) m = fmaxf(m, __shfl_xor_sync(0xffffffffu, m, o));
    float s = 0.0f;
#pragma unroll
    for (int i = 0; i < 5; i++) s += expf(v[i] - m);
#pragma unroll
    for (int o = 1; o < 8; o <<= 1) s += __shfl_xor_sync(0xffffffffu, s, o);
    float lse = m + logf(s);
    if (valid) {
        float* op = out + (long long)gid * 160 + layer * 40;
#pragma unroll
        for (int i = 0; i < 5; i++) op[t + 8 * i] = v[i] - lse;
    }
}

// ---------------- last layer: aggregate in 40-dim + bias + log_softmax --------
__global__ void agg40_kernel(const float* __restrict__ P, const float* __restrict__ bias,
                             float* __restrict__ out) {
    int gid = blockIdx.x * (blockDim.x >> 3) + (threadIdx.x >> 3);
    int t = threadIdx.x & 7;
    bool valid = gid < NN;
    float v[5];
    int beg = 0, end = 0;
    if (valid) {
        float dinv = g_dinv[gid];
        float c0 = dinv * dinv;
#pragma unroll
        for (int i = 0; i < 5; i++) v[i] = P[(long long)gid * 64 + t + 8 * i] * c0;
        beg = g_rowptr[gid];
        end = g_rowptr[gid + 1];
    } else {
#pragma unroll
        for (int i = 0; i < 5; i++) v[i] = 0.0f;
    }
    for (int j = beg; j < end; j++) {
        int s = g_csr_src[j];
        float c = g_csr_coef[j];
#pragma unroll
        for (int i = 0; i < 5; i++) v[i] += c * __ldg(&P[(long long)s * 64 + t + 8 * i]);
    }
#pragma unroll
    for (int i = 0; i < 5; i++) v[i] += bias[t + 8 * i];
    float m = fmaxf(fmaxf(fmaxf(v[0], v[1]), fmaxf(v[2], v[3])), v[4]);
#pragma unroll
    for (int o = 1; o < 8; o <<= 1) m = fmaxf(m, __shfl_xor_sync(0xffffffffu, m, o));
    float s = 0.0f;
#pragma unroll
    for (int i = 0; i < 5; i++) s += expf(v[i] - m);
#pragma unroll
    for (int o = 1; o < 8; o <<= 1) s += __shfl_xor_sync(0xffffffffu, s, o);
    float lse = m + logf(s);
    if (valid) {
        float* op = out + (long long)gid * 160 + 3 * 40;
#pragma unroll
        for (int i = 0; i < 5; i++) op[t + 8 * i] = v[i] - lse;
    }
}

// ---------------- launch -------------------------------------------------------
extern "C" void kernel_launch(void* const* d_in, const int* in_sizes, int n_in,
                              void* d_out, int out_size) {
    const float* x   = (const float*)d_in[0];
    const void*  ei  = d_in[1];
    const float* Wc0 = (const float*)d_in[2];
    const float* bc0 = (const float*)d_in[3];
    const float* Wc1 = (const float*)d_in[4];
    const float* bc1 = (const float*)d_in[5];
    // d_in[6], d_in[7] (Wc2, bc2): dead — final Wc output is never used
    const float* We0 = (const float*)d_in[8];
    const float* be0 = (const float*)d_in[9];
    const float* We1 = (const float*)d_in[10];
    const float* be1 = (const float*)d_in[11];
    const float* We2 = (const float*)d_in[12];
    const float* be2 = (const float*)d_in[13];
    const float* We3 = (const float*)d_in[14];
    const float* be3 = (const float*)d_in[15];
    float* out = (float*)d_out;
    int E = in_sizes[1] / 2;

    float *h1, *h2, *p64, *wp;
    cudaGetSymbolAddress((void**)&h1,  g_h1);
    cudaGetSymbolAddress((void**)&h2,  g_h2);
    cudaGetSymbolAddress((void**)&p64, g_p64);
    cudaGetSymbolAddress((void**)&wp,  g_Wp);
    float* wp0 = wp;
    float* wp1 = wp + 1 * 256 * 64;
    float* wp2 = wp + 2 * 256 * 64;
    float* wp3 = wp + 3 * 256 * 64;

    int nb = (NN + 1023) / 1024;

    // graph preprocessing: degrees, dinv, CSR
    detect_kernel<<<1, 32>>>((const int*)ei);
    zero_deg_kernel<<<(NN + 255) / 256, 256>>>();
    count_kernel<<<(E + 255) / 256, 256>>>(ei, E);
    dinv_kernel<<<(NN + 255) / 256, 256>>>();
    scan1_kernel<<<nb, 1024>>>();
    scan2_kernel<<<1, 32>>>(nb);
    scan3_kernel<<<(NN + 255) / 256, 256>>>();
    fill_kernel<<<(E + 255) / 256, 256>>>(ei, E);

    // pad projection weights to 64 cols
    pad_w_kernel<<<(128 * 64 + 255) / 256, 256>>>(We0, wp0, 128);
    pad_w_kernel<<<(128 * 64 + 255) / 256, 256>>>(We1, wp1, 128);
    pad_w_kernel<<<(256 * 64 + 255) / 256, 256>>>(We2, wp2, 256);
    pad_w_kernel<<<(256 * 64 + 255) / 256, 256>>>(We3, wp3, 256);

    dim3 g1((NN + 127) / 128, 1);
    dim3 g4((NN + 127) / 128, 4);
    int  gs = (NN + 31) / 32;     // softmax/agg40 grid (32 nodes / 256-thr block)
    int  ga = (NN + 7) / 8;       // agg grid (8 warps / block)

    // layer 0: log_softmax(x @ We0 + be0)
    mma_gemm_kernel<128, 64, false><<<g1, 256>>>(x, wp0, nullptr, p64);
    softmax40_kernel<<<gs, 256>>>(p64, be0, out, 0);

    // agg1 (d=128)
    agg_kernel<128><<<ga, 256>>>(x, h1);
    mma_gemm_kernel<128, 64, false><<<g1, 256>>>(h1, wp1, nullptr, p64);
    softmax40_kernel<<<gs, 256>>>(p64, be1, out, 1);
    mma_gemm_kernel<128, 256, true><<<g4, 256>>>(h1, Wc0, bc0, h2);

    // agg2 (d=256)
    agg_kernel<256><<<ga, 256>>>(h2, h1);
    mma_gemm_kernel<256, 64, false><<<g1, 256>>>(h1, wp2, nullptr, p64);
    softmax40_kernel<<<gs, 256>>>(p64, be2, out, 2);
    mma_gemm_kernel<256, 256, true><<<g4, 256>>>(h1, Wc1, bc1, h2);

    // layer 3: agg(h) @ We3 == agg(h @ We3)  -> aggregate in 40-dim (6.4x less traffic)
    mma_gemm_kernel<256, 64, false><<<g1, 256>>>(h2, wp3, nullptr, p64);
    agg40_kernel<<<gs, 256>>>(p64, be3, out);
}

// round 3
// speedup vs baseline: 1.8006x; 1.2491x over previous
#include <cuda_runtime.h>
#include <cuda_fp16.h>
#include <math.h>

#define NN 100000
#define EE 1600000

// ---------------- scratch (static device globals; no allocs allowed) ----------
__device__ float  g_h1[NN * 256];
__device__ float  g_h2[NN * 256];
__device__ float  g_h3[NN * 256];
__device__ __half g_xh[NN * 128];
__device__ __half g_h2h[NN * 256];
__device__ __half g_p64h[NN * 64];
__device__ float  g_p64[NN * 64];
__device__ float  g_dinv[NN];
__device__ int    g_deg[NN];
__device__ int    g_rowptr[NN + 1];
__device__ int    g_cursor[NN];
__device__ int    g_csr_src[EE];
__device__ float  g_csr_coef[EE];
__device__ int    g_blksum[128];
__device__ int    g_blkoff[128];
__device__ int    g_is64;
__device__ float  g_Wp[4 * 256 * 64];   // padded projection weights (cols 40..63 zero)

// ---------------- edge index dtype handling ----------------------------------
__device__ __forceinline__ int edge_at(const void* ei, long long idx) {
    if (g_is64) return (int)((const long long*)ei)[idx];
    return ((const int*)ei)[idx];
}

__global__ void detect_kernel(const int* ei32) {
    if (threadIdx.x == 0) {
        int nz = 0;
        for (int i = 0; i < 64; i++) nz |= ei32[2 * i + 1];
        g_is64 = (nz == 0) ? 1 : 0;
    }
}

// ---------------- degree / dinv ----------------------------------------------
__global__ void zero_deg_kernel() {
    int i = blockIdx.x * blockDim.x + threadIdx.x;
    if (i < NN) g_deg[i] = 0;
}

__global__ void count_kernel(const void* ei, int E) {
    int e = blockIdx.x * blockDim.x + threadIdx.x;
    if (e >= E) return;
    int d = edge_at(ei, (long long)E + e);
    atomicAdd(&g_deg[d], 1);
}

__global__ void dinv_kernel() {
    int i = blockIdx.x * blockDim.x + threadIdx.x;
    if (i < NN) g_dinv[i] = rsqrtf((float)g_deg[i] + 1.0f);
}

// ---------------- exclusive scan (3 kernels) ----------------------------------
__global__ void scan1_kernel() {
    __shared__ int s[1024];
    int t = threadIdx.x;
    int idx = blockIdx.x * 1024 + t;
    int v = (idx < NN) ? g_deg[idx] : 0;
    s[t] = v;
    __syncthreads();
    for (int o = 1; o < 1024; o <<= 1) {
        int x = (t >= o) ? s[t - o] : 0;
        __syncthreads();
        s[t] += x;
        __syncthreads();
    }
    if (idx < NN) g_rowptr[idx] = s[t] - v;
    if (t == 1023) g_blksum[blockIdx.x] = s[t];
}

__global__ void scan2_kernel(int nb) {
    if (threadIdx.x == 0 && blockIdx.x == 0) {
        int running = 0;
        for (int b = 0; b < nb; b++) {
            g_blkoff[b] = running;
            running += g_blksum[b];
        }
        g_rowptr[NN] = running;
    }
}

__global__ void scan3_kernel() {
    int i = blockIdx.x * blockDim.x + threadIdx.x;
    if (i < NN) {
        int r = g_rowptr[i] + g_blkoff[i >> 10];
        g_rowptr[i] = r;
        g_cursor[i] = r;
    }
}

__global__ void fill_kernel(const void* ei, int E) {
    int e = blockIdx.x * blockDim.x + threadIdx.x;
    if (e >= E) return;
    int s = edge_at(ei, e);
    int d = edge_at(ei, (long long)E + e);
    int pos = atomicAdd(&g_cursor[d], 1);
    g_csr_src[pos] = s;
    g_csr_coef[pos] = g_dinv[s] * g_dinv[d];
}

// ---------------- fp32 -> fp16 convert ----------------------------------------
__global__ void convert_half_kernel(const float* __restrict__ in, __half* __restrict__ o, int n4) {
    int i = blockIdx.x * blockDim.x + threadIdx.x;
    if (i >= n4) return;
    float4 v = *(const float4*)&in[i * 4];
    __half2 a = __floats2half2_rn(v.x, v.y);
    __half2 b = __floats2half2_rn(v.z, v.w);
    uint2 u;
    u.x = *(unsigned*)&a;
    u.y = *(unsigned*)&b;
    *(uint2*)&o[i * 4] = u;
}

// ---------------- half FMA helpers --------------------------------------------
__device__ __forceinline__ void acc_u2(float* a, unsigned lo, unsigned hi, float c) {
    float2 f0 = __half22float2(*reinterpret_cast<__half2*>(&lo));
    float2 f1 = __half22float2(*reinterpret_cast<__half2*>(&hi));
    a[0] = fmaf(c, f0.x, a[0]);
    a[1] = fmaf(c, f0.y, a[1]);
    a[2] = fmaf(c, f1.x, a[2]);
    a[3] = fmaf(c, f1.y, a[3]);
}

// ---------------- aggregation: warp per node, half gather, fp32 accumulate ----
template <int D>
__global__ void agg_half_kernel(const __half* __restrict__ h, float* __restrict__ out) {
    const int U2 = D / 4;         // uint2 per row
    const int NU = U2 / 32;       // uint2 per lane (1 for D=128, 2 for D=256)
    int warp = (blockIdx.x * blockDim.x + threadIdx.x) >> 5;
    int lane = threadIdx.x & 31;
    if (warp >= NN) return;
    const uint2* hv = (const uint2*)h;
    float dinv = g_dinv[warp];
    float c0 = dinv * dinv;
    float acc[NU * 4];
#pragma unroll
    for (int i = 0; i < NU * 4; i++) acc[i] = 0.0f;
#pragma unroll
    for (int i = 0; i < NU; i++) {
        uint2 u = hv[warp * U2 + lane + 32 * i];
        acc_u2(&acc[4 * i], u.x, u.y, c0);
    }
    int beg = g_rowptr[warp], end = g_rowptr[warp + 1];
    int j = beg;
    for (; j + 1 < end; j += 2) {
        int   sA = g_csr_src[j],  sB = g_csr_src[j + 1];
        float cA = g_csr_coef[j], cB = g_csr_coef[j + 1];
        uint2 vA[NU], vB[NU];
#pragma unroll
        for (int i = 0; i < NU; i++) vA[i] = __ldg(&hv[sA * U2 + lane + 32 * i]);
#pragma unroll
        for (int i = 0; i < NU; i++) vB[i] = __ldg(&hv[sB * U2 + lane + 32 * i]);
#pragma unroll
        for (int i = 0; i < NU; i++) {
            acc_u2(&acc[4 * i], vA[i].x, vA[i].y, cA);
            acc_u2(&acc[4 * i], vB[i].x, vB[i].y, cB);
        }
    }
    if (j < end) {
        int s = g_csr_src[j];
        float c = g_csr_coef[j];
#pragma unroll
        for (int i = 0; i < NU; i++) {
            uint2 v = __ldg(&hv[s * U2 + lane + 32 * i]);
            acc_u2(&acc[4 * i], v.x, v.y, c);
        }
    }
    float4* ov = (float4*)out;   // row = D floats = D/4 float4
#pragma unroll
    for (int i = 0; i < NU; i++)
        ov[warp * U2 + lane + 32 * i] =
            make_float4(acc[4 * i], acc[4 * i + 1], acc[4 * i + 2], acc[4 * i + 3]);
}

// ---------------- pad projection weights to 64 cols ---------------------------
__global__ void pad_w_kernel(const float* __restrict__ W, float* __restrict__ Wp, int K) {
    int idx = blockIdx.x * blockDim.x + threadIdx.x;
    if (idx >= K * 64) return;
    int k = idx >> 6, j = idx & 63;
    Wp[idx] = (j < 40) ? W[k * 40 + j] : 0.0f;
}

// ---------------- TF32 tensor-core GEMM ---------------------------------------
__device__ __forceinline__ unsigned f2tf32(float f) {
    unsigned u;
    asm("cvt.rna.tf32.f32 %0, %1;" : "=r"(u) : "f"(f));
    return u;
}

__device__ __forceinline__ void mma_tf32(float* c, const unsigned* a, const unsigned* b) {
    asm volatile(
        "mma.sync.aligned.m16n8k8.row.col.f32.tf32.tf32.f32 "
        "{%0,%1,%2,%3}, {%4,%5,%6,%7}, {%8,%9}, {%0,%1,%2,%3};"
        : "+f"(c[0]), "+f"(c[1]), "+f"(c[2]), "+f"(c[3])
        : "r"(a[0]), "r"(a[1]), "r"(a[2]), "r"(a[3]), "r"(b[0]), "r"(b[1]));
}

// C[N,M] = A[N,K] @ W[K,M] (+bias,relu). BM=128, BN=64, BK=32, 256 threads.
template <int K, int M, bool BIAS_RELU, bool OUTH>
__global__ void __launch_bounds__(256)
mma_gemm_kernel(const float* __restrict__ A, const float* __restrict__ W,
                const float* __restrict__ bias, void* __restrict__ Cv) {
    const int BK = 32;
    __shared__ __align__(16) unsigned As[128][BK + 4];   // stride 36
    __shared__ __align__(16) unsigned Bs[BK][64 + 4];    // stride 68
    const int t = threadIdx.x;
    const int lane = t & 31;
    const int warp = t >> 5;
    const int wm = warp & 3;
    const int wn = warp >> 2;
    const int bm = blockIdx.x * 128;
    const int bn = blockIdx.y * 64;

    float acc[2][4][4];
#pragma unroll
    for (int mi = 0; mi < 2; mi++)
#pragma unroll
        for (int ni = 0; ni < 4; ni++)
#pragma unroll
            for (int r = 0; r < 4; r++) acc[mi][ni][r] = 0.0f;

    for (int k0 = 0; k0 < K; k0 += BK) {
#pragma unroll
        for (int r = 0; r < 4; r++) {
            int idx = t + r * 256;
            int row = idx >> 3;
            int c4  = idx & 7;
            float4 v = make_float4(0.f, 0.f, 0.f, 0.f);
            if (bm + row < NN)
                v = *(const float4*)&A[(long long)(bm + row) * K + k0 + c4 * 4];
            uint4 u;
            u.x = f2tf32(v.x); u.y = f2tf32(v.y); u.z = f2tf32(v.z); u.w = f2tf32(v.w);
            *(uint4*)&As[row][c4 * 4] = u;
        }
#pragma unroll
        for (int r = 0; r < 2; r++) {
            int idx = t + r * 256;
            int kk = idx >> 4;
            int c4 = idx & 15;
            float4 v = *(const float4*)&W[(long long)(k0 + kk) * M + bn + c4 * 4];
            uint4 u;
            u.x = f2tf32(v.x); u.y = f2tf32(v.y); u.z = f2tf32(v.z); u.w = f2tf32(v.w);
            *(uint4*)&Bs[kk][c4 * 4] = u;
        }
        __syncthreads();
#pragma unroll
        for (int ks = 0; ks < BK / 8; ks++) {
            unsigned a[2][4], b[4][2];
            const int ar = wm * 32 + (lane >> 2);
            const int ac = ks * 8 + (lane & 3);
#pragma unroll
            for (int mi = 0; mi < 2; mi++) {
                a[mi][0] = As[ar + mi * 16][ac];
                a[mi][1] = As[ar + mi * 16 + 8][ac];
                a[mi][2] = As[ar + mi * 16][ac + 4];
                a[mi][3] = As[ar + mi * 16 + 8][ac + 4];
            }
            const int br = ks * 8 + (lane & 3);
            const int bc = wn * 32 + (lane >> 2);
#pragma unroll
            for (int ni = 0; ni < 4; ni++) {
                b[ni][0] = Bs[br][bc + ni * 8];
                b[ni][1] = Bs[br + 4][bc + ni * 8];
            }
#pragma unroll
            for (int mi = 0; mi < 2; mi++)
#pragma unroll
                for (int ni = 0; ni < 4; ni++)
                    mma_tf32(acc[mi][ni], a[mi], b[ni]);
        }
        __syncthreads();
    }

#pragma unroll
    for (int mi = 0; mi < 2; mi++) {
#pragma unroll
        for (int ni = 0; ni < 4; ni++) {
            int col = bn + wn * 32 + ni * 8 + 2 * (lane & 3);
            float bv0 = 0.f, bv1 = 0.f;
            if (BIAS_RELU) { bv0 = bias[col]; bv1 = bias[col + 1]; }
#pragma unroll
            for (int h = 0; h < 2; h++) {
                int row = bm + wm * 32 + mi * 16 + (lane >> 2) + h * 8;
                if (row < NN) {
                    float v0 = acc[mi][ni][2 * h];
                    float v1 = acc[mi][ni][2 * h + 1];
                    if (BIAS_RELU) {
                        v0 = fmaxf(v0 + bv0, 0.0f);
                        v1 = fmaxf(v1 + bv1, 0.0f);
                    }
                    if (OUTH) {
                        __half2 p = __floats2half2_rn(v0, v1);
                        *(__half2*)&((__half*)Cv)[(long long)row * M + col] = p;
                    } else {
                        *(float2*)&((float*)Cv)[(long long)row * M + col] = make_float2(v0, v1);
                    }
                }
            }
        }
    }
}

// ---------------- bias + log_softmax over 40 cols (8 threads/node) ------------
__global__ void softmax40_kernel(const float* __restrict__ P, const float* __restrict__ bias,
                                 float* __restrict__ out, int layer) {
    int gid = blockIdx.x * (blockDim.x >> 3) + (threadIdx.x >> 3);
    int t = threadIdx.x & 7;
    bool valid = gid < NN;
    float v[5];
#pragma unroll
    for (int i = 0; i < 5; i++)
        v[i] = valid ? (P[(long long)gid * 64 + t + 8 * i] + bias[t + 8 * i]) : 0.0f;
    float m = fmaxf(fmaxf(fmaxf(v[0], v[1]), fmaxf(v[2], v[3])), v[4]);
#pragma unroll
    for (int o = 1; o < 8; o <<= 1) m = fmaxf(m, __shfl_xor_sync(0xffffffffu, m, o));
    float s = 0.0f;
#pragma unroll
    for (int i = 0; i < 5; i++) s += expf(v[i] - m);
#pragma unroll
    for (int o = 1; o < 8; o <<= 1) s += __shfl_xor_sync(0xffffffffu, s, o);
    float lse = m + logf(s);
    if (valid) {
        float* op = out + (long long)gid * 160 + layer * 40;
#pragma unroll
        for (int i = 0; i < 5; i++) op[t + 8 * i] = v[i] - lse;
    }
}

// ---------------- last layer: half 40-dim aggregate + bias + log_softmax ------
// Thread t in [0,8) handles contiguous cols [8t, 8t+8); rows are 64 halves = 128B
// = exactly one L2 line per edge.
__global__ void agg40h_kernel(const __half* __restrict__ P, const float* __restrict__ bias,
                              float* __restrict__ out) {
    int gid = blockIdx.x * (blockDim.x >> 3) + (threadIdx.x >> 3);
    int t = threadIdx.x & 7;
    bool valid = gid < NN;
    bool cvalid = t < 5;   // cols 40..63 are padding
    float v[8];
#pragma unroll
    for (int i = 0; i < 8; i++) v[i] = 0.0f;
    const uint4* Pv = (const uint4*)P;   // 8 uint4 per row
    int beg = 0, end = 0;
    if (valid) {
        float dinv = g_dinv[gid];
        float c0 = dinv * dinv;
        uint4 u = Pv[gid * 8 + t];
        acc_u2(&v[0], u.x, u.y, c0);
        acc_u2(&v[4], u.z, u.w, c0);
        beg = g_rowptr[gid];
        end = g_rowptr[gid + 1];
    }
    for (int j = beg; j < end; j++) {
        int s = g_csr_src[j];
        float c = g_csr_coef[j];
        uint4 u = __ldg(&Pv[s * 8 + t]);
        acc_u2(&v[0], u.x, u.y, c);
        acc_u2(&v[4], u.z, u.w, c);
    }
    float m = -1e30f;
    if (cvalid) {
#pragma unroll
        for (int i = 0; i < 8; i++) {
            v[i] += bias[8 * t + i];
            m = fmaxf(m, v[i]);
        }
    }
#pragma unroll
    for (int o = 1; o < 8; o <<= 1) m = fmaxf(m, __shfl_xor_sync(0xffffffffu, m, o));
    float s = 0.0f;
    if (cvalid) {
#pragma unroll
        for (int i = 0; i < 8; i++) s += expf(v[i] - m);
    }
#pragma unroll
    for (int o = 1; o < 8; o <<= 1) s += __shfl_xor_sync(0xffffffffu, s, o);
    float lse = m + logf(s);
    if (valid && cvalid) {
        float* op = out + (long long)gid * 160 + 120 + 8 * t;
        *(float4*)&op[0] = make_float4(v[0] - lse, v[1] - lse, v[2] - lse, v[3] - lse);
        *(float4*)&op[4] = make_float4(v[4] - lse, v[5] - lse, v[6] - lse, v[7] - lse);
    }
}

// ---------------- launch -------------------------------------------------------
extern "C" void kernel_launch(void* const* d_in, const int* in_sizes, int n_in,
                              void* d_out, int out_size) {
    const float* x   = (const float*)d_in[0];
    const void*  ei  = d_in[1];
    const float* Wc0 = (const float*)d_in[2];
    const float* bc0 = (const float*)d_in[3];
    const float* Wc1 = (const float*)d_in[4];
    const float* bc1 = (const float*)d_in[5];
    // d_in[6], d_in[7] (Wc2, bc2): dead — final Wc output is never used
    const float* We0 = (const float*)d_in[8];
    const float* be0 = (const float*)d_in[9];
    const float* We1 = (const float*)d_in[10];
    const float* be1 = (const float*)d_in[11];
    const float* We2 = (const float*)d_in[12];
    const float* be2 = (const float*)d_in[13];
    const float* We3 = (const float*)d_in[14];
    const float* be3 = (const float*)d_in[15];
    float* out = (float*)d_out;
    int E = in_sizes[1] / 2;

    float *h1, *h2, *h3, *p64, *wp;
    __half *xh, *h2h, *p64h;
    cudaGetSymbolAddress((void**)&h1,   g_h1);
    cudaGetSymbolAddress((void**)&h2,   g_h2);
    cudaGetSymbolAddress((void**)&h3,   g_h3);
    cudaGetSymbolAddress((void**)&p64,  g_p64);
    cudaGetSymbolAddress((void**)&wp,   g_Wp);
    cudaGetSymbolAddress((void**)&xh,   g_xh);
    cudaGetSymbolAddress((void**)&h2h,  g_h2h);
    cudaGetSymbolAddress((void**)&p64h, g_p64h);
    float* wp0 = wp;
    float* wp1 = wp + 1 * 256 * 64;
    float* wp2 = wp + 2 * 256 * 64;
    float* wp3 = wp + 3 * 256 * 64;

    // streams/events: created once (host-side resources only; device work per
    // call is identical every call)
    static cudaStream_t s1 = nullptr;
    static cudaEvent_t evStart, evPre, evA1, evA2, evS1;
    if (!s1) {
        cudaStreamCreateWithFlags(&s1, cudaStreamNonBlocking);
        cudaEventCreateWithFlags(&evStart, cudaEventDisableTiming);
        cudaEventCreateWithFlags(&evPre,   cudaEventDisableTiming);
        cudaEventCreateWithFlags(&evA1,    cudaEventDisableTiming);
        cudaEventCreateWithFlags(&evA2,    cudaEventDisableTiming);
        cudaEventCreateWithFlags(&evS1,    cudaEventDisableTiming);
    }

    int nb = (NN + 1023) / 1024;
    dim3 g1((NN + 127) / 128, 1);
    dim3 g4((NN + 127) / 128, 4);
    int  gs = (NN + 31) / 32;
    int  ga = (NN + 7) / 8;

    // fork side branch
    cudaEventRecord(evStart, 0);
    cudaStreamWaitEvent(s1, evStart, 0);

    // s1: x->half, weight pads, layer-0 projection (independent of CSR)
    convert_half_kernel<<<(NN * 128 / 4 + 255) / 256, 256, 0, s1>>>(x, xh, NN * 128 / 4);
    pad_w_kernel<<<(128 * 64 + 255) / 256, 256, 0, s1>>>(We0, wp0, 128);
    pad_w_kernel<<<(128 * 64 + 255) / 256, 256, 0, s1>>>(We1, wp1, 128);
    pad_w_kernel<<<(256 * 64 + 255) / 256, 256, 0, s1>>>(We2, wp2, 256);
    pad_w_kernel<<<(256 * 64 + 255) / 256, 256, 0, s1>>>(We3, wp3, 256);
    cudaEventRecord(evPre, s1);
    mma_gemm_kernel<128, 64, false, false><<<g1, 256, 0, s1>>>(x, wp0, nullptr, p64);
    softmax40_kernel<<<gs, 256, 0, s1>>>(p64, be0, out, 0);

    // main stream: CSR preprocessing (overlaps s1 branch)
    detect_kernel<<<1, 32>>>((const int*)ei);
    zero_deg_kernel<<<(NN + 255) / 256, 256>>>();
    count_kernel<<<(E + 255) / 256, 256>>>(ei, E);
    dinv_kernel<<<(NN + 255) / 256, 256>>>();
    scan1_kernel<<<nb, 1024>>>();
    scan2_kernel<<<1, 32>>>(nb);
    scan3_kernel<<<(NN + 255) / 256, 256>>>();
    fill_kernel<<<(E + 255) / 256, 256>>>(ei, E);

    // main chain: aggregations + Wc GEMMs
    cudaStreamWaitEvent(0, evPre, 0);                 // xh + padded weights ready
    agg_half_kernel<128><<<ga, 256>>>(xh, h1);
    cudaEventRecord(evA1, 0);
    mma_gemm_kernel<128, 256, true, true><<<g4, 256>>>(h1, Wc0, bc0, h2h);
    agg_half_kernel<256><<<ga, 256>>>(h2h, h2);
    cudaEventRecord(evA2, 0);
    mma_gemm_kernel<256, 256, true, false><<<g4, 256>>>(h2, Wc1, bc1, h3);
    mma_gemm_kernel<256, 64, false, true><<<g1, 256>>>(h3, wp3, nullptr, p64h);
    agg40h_kernel<<<gs, 256>>>(p64h, be3, out);

    // s1: per-layer projections overlap the Wc GEMMs / aggs
    cudaStreamWaitEvent(s1, evA1, 0);
    mma_gemm_kernel<128, 64, false, false><<<g1, 256, 0, s1>>>(h1, wp1, nullptr, p64);
    softmax40_kernel<<<gs, 256, 0, s1>>>(p64, be1, out, 1);
    cudaStreamWaitEvent(s1, evA2, 0);
    mma_gemm_kernel<256, 64, false, false><<<g1, 256, 0, s1>>>(h2, wp2, nullptr, p64);
    softmax40_kernel<<<gs, 256, 0, s1>>>(p64, be2, out, 2);
    cudaEventRecord(evS1, s1);

    // join before capture ends
    cudaStreamWaitEvent(0, evS1, 0);
}

// round 4
// speedup vs baseline: 2.6722x; 1.4840x over previous
#include <cuda_runtime.h>
#include <cuda_fp16.h>
#include <math.h>

#define NN 100000
#define EE 1600000

// ---------------- scratch (static device globals; no allocs allowed) ----------
__device__ __half g_xh[NN * 128];
__device__ __half g_h1h[NN * 128];
__device__ __half g_h2h[NN * 256];
__device__ __half g_h2ah[NN * 256];
__device__ __half g_h3h[NN * 256];
__device__ __half g_p64h[NN * 64];
__device__ float  g_p64[NN * 64];
__device__ float  g_dinv[NN];
__device__ int    g_deg[NN];
__device__ int    g_rowptr[NN + 1];
__device__ int    g_cursor[NN];
__device__ int    g_csr_src[EE];
__device__ float  g_csr_coef[EE];
__device__ int    g_blksum[128];
__device__ int    g_blkoff[128];
__device__ int    g_is64;
__device__ __half g_Wph[4 * 256 * 64];    // padded projection weights, half
__device__ __half g_Wc0h[128 * 256];
__device__ __half g_Wc1h[256 * 256];

// ---------------- edge index dtype handling ----------------------------------
__device__ __forceinline__ int edge_at(const void* ei, long long idx) {
    if (g_is64) return (int)((const long long*)ei)[idx];
    return ((const int*)ei)[idx];
}

// zero degrees + detect edge dtype in one kernel
__global__ void init_kernel(const int* ei32) {
    int i = blockIdx.x * blockDim.x + threadIdx.x;
    if (i < NN) g_deg[i] = 0;
    if (blockIdx.x == 0 && threadIdx.x == 0) {
        int nz = 0;
        for (int k = 0; k < 64; k++) nz |= ei32[2 * k + 1];
        g_is64 = (nz == 0) ? 1 : 0;   // int64 LE: hi-words all zero
    }
}

__global__ void count_kernel(const void* ei, int E) {
    int e = blockIdx.x * blockDim.x + threadIdx.x;
    if (e >= E) return;
    int d = edge_at(ei, (long long)E + e);
    atomicAdd(&g_deg[d], 1);
}

// scan over degrees (block-local) + dinv computed on load
__global__ void scan1_kernel() {
    __shared__ int s[1024];
    int t = threadIdx.x;
    int idx = blockIdx.x * 1024 + t;
    int v = (idx < NN) ? g_deg[idx] : 0;
    if (idx < NN) g_dinv[idx] = rsqrtf((float)v + 1.0f);
    s[t] = v;
    __syncthreads();
    for (int o = 1; o < 1024; o <<= 1) {
        int x = (t >= o) ? s[t - o] : 0;
        __syncthreads();
        s[t] += x;
        __syncthreads();
    }
    if (idx < NN) g_rowptr[idx] = s[t] - v;
    if (t == 1023) g_blksum[blockIdx.x] = s[t];
}

__global__ void scan2_kernel(int nb) {
    if (threadIdx.x == 0 && blockIdx.x == 0) {
        int running = 0;
        for (int b = 0; b < nb; b++) {
            g_blkoff[b] = running;
            running += g_blksum[b];
        }
        g_rowptr[NN] = running;
    }
}

__global__ void scan3_kernel() {
    int i = blockIdx.x * blockDim.x + threadIdx.x;
    if (i < NN) {
        int r = g_rowptr[i] + g_blkoff[i >> 10];
        g_rowptr[i] = r;
        g_cursor[i] = r;
    }
}

__global__ void fill_kernel(const void* ei, int E) {
    int e = blockIdx.x * blockDim.x + threadIdx.x;
    if (e >= E) return;
    int s = edge_at(ei, e);
    int d = edge_at(ei, (long long)E + e);
    int pos = atomicAdd(&g_cursor[d], 1);
    g_csr_src[pos] = s;
    g_csr_coef[pos] = g_dinv[s] * g_dinv[d];
}

// ---------------- fp32 -> fp16 convert ----------------------------------------
__global__ void convert_half_kernel(const float* __restrict__ in, __half* __restrict__ o, int n4) {
    int i = blockIdx.x * blockDim.x + threadIdx.x;
    if (i >= n4) return;
    float4 v = *(const float4*)&in[i * 4];
    __half2 a = __floats2half2_rn(v.x, v.y);
    __half2 b = __floats2half2_rn(v.z, v.w);
    uint2 u;
    u.x = *(unsigned*)&a;
    u.y = *(unsigned*)&b;
    *(uint2*)&o[i * 4] = u;
}

// pad [K,40] fp32 projection weights to [K,64] half (cols 40..63 zero)
__global__ void pad_wh_kernel(const float* __restrict__ W, __half* __restrict__ Wp, int K) {
    int idx = blockIdx.x * blockDim.x + threadIdx.x;
    if (idx >= K * 64) return;
    int k = idx >> 6, j = idx & 63;
    Wp[idx] = __float2half((j < 40) ? W[k * 40 + j] : 0.0f);
}

// ---------------- half FMA helper ---------------------------------------------
__device__ __forceinline__ void acc_u2(float* a, unsigned lo, unsigned hi, float c) {
    float2 f0 = __half22float2(*reinterpret_cast<__half2*>(&lo));
    float2 f1 = __half22float2(*reinterpret_cast<__half2*>(&hi));
    a[0] = fmaf(c, f0.x, a[0]);
    a[1] = fmaf(c, f0.y, a[1]);
    a[2] = fmaf(c, f1.x, a[2]);
    a[3] = fmaf(c, f1.y, a[3]);
}

// ---------------- aggregation: warp/node, half gather, fp32 acc, half out -----
template <int D>
__global__ void agg_half_kernel(const __half* __restrict__ h, __half* __restrict__ out) {
    const int U2 = D / 4;         // uint2 (4 halves) per row
    const int NU = U2 / 32;       // uint2 per lane
    int warp = (blockIdx.x * blockDim.x + threadIdx.x) >> 5;
    int lane = threadIdx.x & 31;
    if (warp >= NN) return;
    const uint2* hv = (const uint2*)h;
    float dinv = g_dinv[warp];
    float c0 = dinv * dinv;
    float acc[NU * 4];
#pragma unroll
    for (int i = 0; i < NU * 4; i++) acc[i] = 0.0f;
#pragma unroll
    for (int i = 0; i < NU; i++) {
        uint2 u = hv[warp * U2 + lane + 32 * i];
        acc_u2(&acc[4 * i], u.x, u.y, c0);
    }
    int beg = g_rowptr[warp], end = g_rowptr[warp + 1];
    int j = beg;
    for (; j + 1 < end; j += 2) {
        int   sA = g_csr_src[j],  sB = g_csr_src[j + 1];
        float cA = g_csr_coef[j], cB = g_csr_coef[j + 1];
        uint2 vA[NU], vB[NU];
#pragma unroll
        for (int i = 0; i < NU; i++) vA[i] = __ldg(&hv[sA * U2 + lane + 32 * i]);
#pragma unroll
        for (int i = 0; i < NU; i++) vB[i] = __ldg(&hv[sB * U2 + lane + 32 * i]);
#pragma unroll
        for (int i = 0; i < NU; i++) {
            acc_u2(&acc[4 * i], vA[i].x, vA[i].y, cA);
            acc_u2(&acc[4 * i], vB[i].x, vB[i].y, cB);
        }
    }
    if (j < end) {
        int s = g_csr_src[j];
        float c = g_csr_coef[j];
#pragma unroll
        for (int i = 0; i < NU; i++) {
            uint2 v = __ldg(&hv[s * U2 + lane + 32 * i]);
            acc_u2(&acc[4 * i], v.x, v.y, c);
        }
    }
    uint2* ov = (uint2*)out;
#pragma unroll
    for (int i = 0; i < NU; i++) {
        __half2 p0 = __floats2half2_rn(acc[4 * i], acc[4 * i + 1]);
        __half2 p1 = __floats2half2_rn(acc[4 * i + 2], acc[4 * i + 3]);
        uint2 u;
        u.x = *(unsigned*)&p0;
        u.y = *(unsigned*)&p1;
        ov[warp * U2 + lane + 32 * i] = u;
    }
}

// ---------------- fp16 tensor-core GEMM ---------------------------------------
__device__ __forceinline__ void mma_f16(float* c, const unsigned* a, const unsigned* b) {
    asm volatile(
        "mma.sync.aligned.m16n8k16.row.col.f32.f16.f16.f32 "
        "{%0,%1,%2,%3}, {%4,%5,%6,%7}, {%8,%9}, {%0,%1,%2,%3};"
        : "+f"(c[0]), "+f"(c[1]), "+f"(c[2]), "+f"(c[3])
        : "r"(a[0]), "r"(a[1]), "r"(a[2]), "r"(a[3]), "r"(b[0]), "r"(b[1]));
}

// C[N,M] = A[N,K] @ W[K,M] (+bias,relu). Half inputs, fp32 accum.
// BM=128, BN=64, BK=32, 256 threads; 8 warps 4x2; warp tile 32x32.
template <int K, int M, bool BIAS_RELU, bool OUTH>
__global__ void __launch_bounds__(256)
hgemm_kernel(const __half* __restrict__ A, const __half* __restrict__ W,
             const float* __restrict__ bias, void* __restrict__ Cv) {
    const int BK = 32;
    __shared__ __align__(16) __half As[128][40];   // row-major, stride 40 halves
    __shared__ __align__(16) __half Bs[64][34];    // transposed [n][k], stride 34
    const int t = threadIdx.x;
    const int lane = t & 31;
    const int warp = t >> 5;
    const int wm = warp & 3;
    const int wn = warp >> 2;
    const int bm = blockIdx.x * 128;
    const int bn = blockIdx.y * 64;

    float acc[2][4][4];
#pragma unroll
    for (int mi = 0; mi < 2; mi++)
#pragma unroll
        for (int ni = 0; ni < 4; ni++)
#pragma unroll
            for (int r = 0; r < 4; r++) acc[mi][ni][r] = 0.0f;

    for (int k0 = 0; k0 < K; k0 += BK) {
        // stage A: 128 rows x 32 halves = 512 uint4, 2 per thread
#pragma unroll
        for (int r = 0; r < 2; r++) {
            int idx = t + r * 256;
            int row = idx >> 2, c4 = idx & 3;
            uint4 u = make_uint4(0, 0, 0, 0);
            if (bm + row < NN)
                u = *(const uint4*)&A[(long long)(bm + row) * K + k0 + c4 * 8];
            *(uint4*)&As[row][c4 * 8] = u;
        }
        // stage B transposed: 32 k-rows x 64 cols, 1 uint4 per thread
        {
            int kk = t >> 3, c8 = t & 7;
            uint4 u = *(const uint4*)&W[(long long)(k0 + kk) * M + bn + c8 * 8];
            const __half* hp = (const __half*)&u;
#pragma unroll
            for (int i = 0; i < 8; i++) Bs[c8 * 8 + i][kk] = hp[i];
        }
        __syncthreads();
#pragma unroll
        for (int ks = 0; ks < 2; ks++) {
            unsigned a[2][4], b[4][2];
            const int ar = wm * 32 + (lane >> 2);
            const int ac = ks * 16 + (lane & 3) * 2;
#pragma unroll
            for (int mi = 0; mi < 2; mi++) {
                a[mi][0] = *(const unsigned*)&As[ar + mi * 16][ac];
                a[mi][1] = *(const unsigned*)&As[ar + mi * 16 + 8][ac];
                a[mi][2] = *(const unsigned*)&As[ar + mi * 16][ac + 8];
                a[mi][3] = *(const unsigned*)&As[ar + mi * 16 + 8][ac + 8];
            }
            const int bc = wn * 32 + (lane >> 2);
            const int bk = ks * 16 + (lane & 3) * 2;
#pragma unroll
            for (int ni = 0; ni < 4; ni++) {
                b[ni][0] = *(const unsigned*)&Bs[bc + ni * 8][bk];
                b[ni][1] = *(const unsigned*)&Bs[bc + ni * 8][bk + 8];
            }
#pragma unroll
            for (int mi = 0; mi < 2; mi++)
#pragma unroll
                for (int ni = 0; ni < 4; ni++)
                    mma_f16(acc[mi][ni], a[mi], b[ni]);
        }
        __syncthreads();
    }

    // epilogue
#pragma unroll
    for (int mi = 0; mi < 2; mi++) {
#pragma unroll
        for (int ni = 0; ni < 4; ni++) {
            int col = bn + wn * 32 + ni * 8 + 2 * (lane & 3);
            float bv0 = 0.f, bv1 = 0.f;
            if (BIAS_RELU) { bv0 = bias[col]; bv1 = bias[col + 1]; }
#pragma unroll
            for (int h = 0; h < 2; h++) {
                int row = bm + wm * 32 + mi * 16 + (lane >> 2) + h * 8;
                if (row < NN) {
                    float v0 = acc[mi][ni][2 * h];
                    float v1 = acc[mi][ni][2 * h + 1];
                    if (BIAS_RELU) {
                        v0 = fmaxf(v0 + bv0, 0.0f);
                        v1 = fmaxf(v1 + bv1, 0.0f);
                    }
                    if (OUTH) {
                        __half2 p = __floats2half2_rn(v0, v1);
                        *(__half2*)&((__half*)Cv)[(long long)row * M + col] = p;
                    } else {
                        *(float2*)&((float*)Cv)[(long long)row * M + col] = make_float2(v0, v1);
                    }
                }
            }
        }
    }
}

// ---------------- bias + log_softmax over 40 cols (8 threads/node) ------------
__global__ void softmax40_kernel(const float* __restrict__ P, const float* __restrict__ bias,
                                 float* __restrict__ out, int layer) {
    int gid = blockIdx.x * (blockDim.x >> 3) + (threadIdx.x >> 3);
    int t = threadIdx.x & 7;
    bool valid = gid < NN;
    float v[5];
#pragma unroll
    for (int i = 0; i < 5; i++)
        v[i] = valid ? (P[(long long)gid * 64 + t + 8 * i] + bias[t + 8 * i]) : 0.0f;
    float m = fmaxf(fmaxf(fmaxf(v[0], v[1]), fmaxf(v[2], v[3])), v[4]);
#pragma unroll
    for (int o = 1; o < 8; o <<= 1) m = fmaxf(m, __shfl_xor_sync(0xffffffffu, m, o));
    float s = 0.0f;
#pragma unroll
    for (int i = 0; i < 5; i++) s += expf(v[i] - m);
#pragma unroll
    for (int o = 1; o < 8; o <<= 1) s += __shfl_xor_sync(0xffffffffu, s, o);
    float lse = m + logf(s);
    if (valid) {
        float* op = out + (long long)gid * 160 + layer * 40;
#pragma unroll
        for (int i = 0; i < 5; i++) op[t + 8 * i] = v[i] - lse;
    }
}

// ---------------- last layer: half 40-dim aggregate + bias + log_softmax ------
__global__ void agg40h_kernel(const __half* __restrict__ P, const float* __restrict__ bias,
                              float* __restrict__ out) {
    int gid = blockIdx.x * (blockDim.x >> 3) + (threadIdx.x >> 3);
    int t = threadIdx.x & 7;
    bool valid = gid < NN;
    bool cvalid = t < 5;
    float v[8];
#pragma unroll
    for (int i = 0; i < 8; i++) v[i] = 0.0f;
    const uint4* Pv = (const uint4*)P;   // 8 uint4 per 64-half row
    int beg = 0, end = 0;
    if (valid) {
        float dinv = g_dinv[gid];
        float c0 = dinv * dinv;
        uint4 u = Pv[gid * 8 + t];
        acc_u2(&v[0], u.x, u.y, c0);
        acc_u2(&v[4], u.z, u.w, c0);
        beg = g_rowptr[gid];
        end = g_rowptr[gid + 1];
    }
    for (int j = beg; j < end; j++) {
        int s = g_csr_src[j];
        float c = g_csr_coef[j];
        uint4 u = __ldg(&Pv[s * 8 + t]);
        acc_u2(&v[0], u.x, u.y, c);
        acc_u2(&v[4], u.z, u.w, c);
    }
    float m = -1e30f;
    if (cvalid) {
#pragma unroll
        for (int i = 0; i < 8; i++) {
            v[i] += bias[8 * t + i];
            m = fmaxf(m, v[i]);
        }
    }
#pragma unroll
    for (int o = 1; o < 8; o <<= 1) m = fmaxf(m, __shfl_xor_sync(0xffffffffu, m, o));
    float s = 0.0f;
    if (cvalid) {
#pragma unroll
        for (int i = 0; i < 8; i++) s += expf(v[i] - m);
    }
#pragma unroll
    for (int o = 1; o < 8; o <<= 1) s += __shfl_xor_sync(0xffffffffu, s, o);
    float lse = m + logf(s);
    if (valid && cvalid) {
        float* op = out + (long long)gid * 160 + 120 + 8 * t;
        *(float4*)&op[0] = make_float4(v[0] - lse, v[1] - lse, v[2] - lse, v[3] - lse);
        *(float4*)&op[4] = make_float4(v[4] - lse, v[5] - lse, v[6] - lse, v[7] - lse);
    }
}

// ---------------- launch -------------------------------------------------------
extern "C" void kernel_launch(void* const* d_in, const int* in_sizes, int n_in,
                              void* d_out, int out_size) {
    const float* x   = (const float*)d_in[0];
    const void*  ei  = d_in[1];
    const float* Wc0 = (const float*)d_in[2];
    const float* bc0 = (const float*)d_in[3];
    const float* Wc1 = (const float*)d_in[4];
    const float* bc1 = (const float*)d_in[5];
    // d_in[6], d_in[7] (Wc2, bc2): dead — final Wc output is never used
    const float* We0 = (const float*)d_in[8];
    const float* be0 = (const float*)d_in[9];
    const float* We1 = (const float*)d_in[10];
    const float* be1 = (const float*)d_in[11];
    const float* We2 = (const float*)d_in[12];
    const float* be2 = (const float*)d_in[13];
    const float* We3 = (const float*)d_in[14];
    const float* be3 = (const float*)d_in[15];
    float* out = (float*)d_out;
    int E = in_sizes[1] / 2;

    float* p64;
    __half *xh, *h1h, *h2h, *h2ah, *h3h, *p64h, *wph, *wc0h, *wc1h;
    cudaGetSymbolAddress((void**)&p64,  g_p64);
    cudaGetSymbolAddress((void**)&xh,   g_xh);
    cudaGetSymbolAddress((void**)&h1h,  g_h1h);
    cudaGetSymbolAddress((void**)&h2h,  g_h2h);
    cudaGetSymbolAddress((void**)&h2ah, g_h2ah);
    cudaGetSymbolAddress((void**)&h3h,  g_h3h);
    cudaGetSymbolAddress((void**)&p64h, g_p64h);
    cudaGetSymbolAddress((void**)&wph,  g_Wph);
    cudaGetSymbolAddress((void**)&wc0h, g_Wc0h);
    cudaGetSymbolAddress((void**)&wc1h, g_Wc1h);
    __half* wp0 = wph;
    __half* wp1 = wph + 1 * 256 * 64;
    __half* wp2 = wph + 2 * 256 * 64;
    __half* wp3 = wph + 3 * 256 * 64;

    static cudaStream_t s1 = nullptr;
    static cudaEvent_t evStart, evPre, evA1, evA2, evS1;
    if (!s1) {
        cudaStreamCreateWithFlags(&s1, cudaStreamNonBlocking);
        cudaEventCreateWithFlags(&evStart, cudaEventDisableTiming);
        cudaEventCreateWithFlags(&evPre,   cudaEventDisableTiming);
        cudaEventCreateWithFlags(&evA1,    cudaEventDisableTiming);
        cudaEventCreateWithFlags(&evA2,    cudaEventDisableTiming);
        cudaEventCreateWithFlags(&evS1,    cudaEventDisableTiming);
    }

    int nb = (NN + 1023) / 1024;
    dim3 g1((NN + 127) / 128, 1);
    dim3 g4((NN + 127) / 128, 4);
    int  gs = (NN + 31) / 32;
    int  ga = (NN + 7) / 8;

    // fork side branch
    cudaEventRecord(evStart, 0);
    cudaStreamWaitEvent(s1, evStart, 0);

    // s1: converts + weight prep (independent of CSR), then layer-0 projection
    convert_half_kernel<<<(NN * 128 / 4 + 255) / 256, 256, 0, s1>>>(x, xh, NN * 128 / 4);
    convert_half_kernel<<<(128 * 256 / 4 + 255) / 256, 256, 0, s1>>>(Wc0, wc0h, 128 * 256 / 4);
    convert_half_kernel<<<(256 * 256 / 4 + 255) / 256, 256, 0, s1>>>(Wc1, wc1h, 256 * 256 / 4);
    pad_wh_kernel<<<(128 * 64 + 255) / 256, 256, 0, s1>>>(We0, wp0, 128);
    pad_wh_kernel<<<(128 * 64 + 255) / 256, 256, 0, s1>>>(We1, wp1, 128);
    pad_wh_kernel<<<(256 * 64 + 255) / 256, 256, 0, s1>>>(We2, wp2, 256);
    pad_wh_kernel<<<(256 * 64 + 255) / 256, 256, 0, s1>>>(We3, wp3, 256);
    cudaEventRecord(evPre, s1);
    hgemm_kernel<128, 64, false, false><<<g1, 256, 0, s1>>>(xh, wp0, nullptr, p64);
    softmax40_kernel<<<gs, 256, 0, s1>>>(p64, be0, out, 0);

    // main stream: CSR preprocessing (overlaps s1 branch)
    init_kernel<<<(NN + 255) / 256, 256>>>((const int*)ei);
    count_kernel<<<(E + 255) / 256, 256>>>(ei, E);
    scan1_kernel<<<nb, 1024>>>();
    scan2_kernel<<<1, 32>>>(nb);
    scan3_kernel<<<(NN + 255) / 256, 256>>>();
    fill_kernel<<<(E + 255) / 256, 256>>>(ei, E);

    // main chain
    cudaStreamWaitEvent(0, evPre, 0);                 // xh + half weights ready
    agg_half_kernel<128><<<ga, 256>>>(xh, h1h);
    cudaEventRecord(evA1, 0);
    hgemm_kernel<128, 256, true, true><<<g4, 256>>>(h1h, wc0h, bc0, h2h);
    agg_half_kernel<256><<<ga, 256>>>(h2h, h2ah);
    cudaEventRecord(evA2, 0);
    hgemm_kernel<256, 256, true, true><<<g4, 256>>>(h2ah, wc1h, bc1, h3h);
    hgemm_kernel<256, 64, false, true><<<g1, 256>>>(h3h, wp3, nullptr, p64h);
    agg40h_kernel<<<gs, 256>>>(p64h, be3, out);

    // s1: per-layer projections overlap the Wc GEMMs / aggs
    cudaStreamWaitEvent(s1, evA1, 0);
    hgemm_kernel<128, 64, false, false><<<g1, 256, 0, s1>>>(h1h, wp1, nullptr, p64);
    softmax40_kernel<<<gs, 256, 0, s1>>>(p64, be1, out, 1);
    cudaStreamWaitEvent(s1, evA2, 0);
    hgemm_kernel<256, 64, false, false><<<g1, 256, 0, s1>>>(h2ah, wp2, nullptr, p64);
    softmax40_kernel<<<gs, 256, 0, s1>>>(p64, be2, out, 2);
    cudaEventRecord(evS1, s1);

    // join before capture ends
    cudaStreamWaitEvent(0, evS1, 0);
}

// round 5
// speedup vs baseline: 2.8185x; 1.0547x over previous
#include <cuda_runtime.h>
#include <cuda_fp16.h>
#include <math.h>

#define NN 100000
#define EE 1600000

// ---------------- scratch (static device globals; no allocs allowed) ----------
__device__ __half g_xh[NN * 128];
__device__ __half g_h1h[NN * 128];
__device__ __half g_h2h[NN * 256];
__device__ __half g_h2ah[NN * 256];
__device__ __half g_h3h[NN * 256];
__device__ __half g_p64h[NN * 64];
__device__ float  g_p64[NN * 64];
__device__ float  g_dinv[NN];
__device__ int    g_deg[NN];
__device__ int    g_rowptr[NN + 1];
__device__ int    g_cursor[NN];
__device__ int    g_csr_src[EE];
__device__ float  g_csr_coef[EE];
__device__ int    g_blksum[128];
__device__ int    g_blkoff[128];
__device__ int    g_is64;
__device__ __half g_Wph[4 * 256 * 64];
__device__ __half g_Wc0h[128 * 256];
__device__ __half g_Wc1h[256 * 256];

// ---------------- edge index dtype handling ----------------------------------
__device__ __forceinline__ int edge_at(const void* ei, long long idx) {
    if (g_is64) return (int)((const long long*)ei)[idx];
    return ((const int*)ei)[idx];
}

__global__ void init_kernel(const int* ei32) {
    int i = blockIdx.x * blockDim.x + threadIdx.x;
    if (i < NN) g_deg[i] = 0;
    if (blockIdx.x == 0 && threadIdx.x == 0) {
        int nz = 0;
        for (int k = 0; k < 64; k++) nz |= ei32[2 * k + 1];
        g_is64 = (nz == 0) ? 1 : 0;
    }
}

__global__ void count_kernel(const void* ei, int E) {
    int e = blockIdx.x * blockDim.x + threadIdx.x;
    if (e >= E) return;
    int d = edge_at(ei, (long long)E + e);
    atomicAdd(&g_deg[d], 1);
}

__global__ void scan1_kernel() {
    __shared__ int s[1024];
    int t = threadIdx.x;
    int idx = blockIdx.x * 1024 + t;
    int v = (idx < NN) ? g_deg[idx] : 0;
    if (idx < NN) g_dinv[idx] = rsqrtf((float)v + 1.0f);
    s[t] = v;
    __syncthreads();
    for (int o = 1; o < 1024; o <<= 1) {
        int x = (t >= o) ? s[t - o] : 0;
        __syncthreads();
        s[t] += x;
        __syncthreads();
    }
    if (idx < NN) g_rowptr[idx] = s[t] - v;
    if (t == 1023) g_blksum[blockIdx.x] = s[t];
}

__global__ void scan2_kernel(int nb) {
    if (threadIdx.x == 0 && blockIdx.x == 0) {
        int running = 0;
        for (int b = 0; b < nb; b++) {
            g_blkoff[b] = running;
            running += g_blksum[b];
        }
        g_rowptr[NN] = running;
    }
}

__global__ void scan3_kernel() {
    int i = blockIdx.x * blockDim.x + threadIdx.x;
    if (i < NN) {
        int r = g_rowptr[i] + g_blkoff[i >> 10];
        g_rowptr[i] = r;
        g_cursor[i] = r;
    }
}

__global__ void fill_kernel(const void* ei, int E) {
    int e = blockIdx.x * blockDim.x + threadIdx.x;
    if (e >= E) return;
    int s = edge_at(ei, e);
    int d = edge_at(ei, (long long)E + e);
    int pos = atomicAdd(&g_cursor[d], 1);
    g_csr_src[pos] = s;
    g_csr_coef[pos] = g_dinv[s] * g_dinv[d];
}

// ---------------- fp32 -> fp16 convert ----------------------------------------
__global__ void convert_half_kernel(const float* __restrict__ in, __half* __restrict__ o, int n4) {
    int i = blockIdx.x * blockDim.x + threadIdx.x;
    if (i >= n4) return;
    float4 v = *(const float4*)&in[i * 4];
    __half2 a = __floats2half2_rn(v.x, v.y);
    __half2 b = __floats2half2_rn(v.z, v.w);
    uint2 u;
    u.x = *(unsigned*)&a;
    u.y = *(unsigned*)&b;
    *(uint2*)&o[i * 4] = u;
}

__global__ void pad_wh_kernel(const float* __restrict__ W, __half* __restrict__ Wp, int K) {
    int idx = blockIdx.x * blockDim.x + threadIdx.x;
    if (idx >= K * 64) return;
    int k = idx >> 6, j = idx & 63;
    Wp[idx] = __float2half((j < 40) ? W[k * 40 + j] : 0.0f);
}

// ---------------- half accumulate helpers --------------------------------------
__device__ __forceinline__ void acc_u2(float* a, unsigned lo, unsigned hi, float c) {
    float2 f0 = __half22float2(*reinterpret_cast<__half2*>(&lo));
    float2 f1 = __half22float2(*reinterpret_cast<__half2*>(&hi));
    a[0] = fmaf(c, f0.x, a[0]);
    a[1] = fmaf(c, f0.y, a[1]);
    a[2] = fmaf(c, f1.x, a[2]);
    a[3] = fmaf(c, f1.y, a[3]);
}

__device__ __forceinline__ void acc_u4(float* a, uint4 u, float c) {
    acc_u2(a,     u.x, u.y, c);
    acc_u2(a + 4, u.z, u.w, c);
}

// ---------------- aggregation: LANES lanes/node, uint4 gather, 4-edge pipe ----
// Row = LANES uint4 (LANES*8 halves). LANES=32 -> D=256, LANES=16 -> D=128.
template <int LANES>
__global__ void agg_u4_kernel(const __half* __restrict__ h, __half* __restrict__ out) {
    int gid  = (blockIdx.x * blockDim.x + threadIdx.x) / LANES;
    int lane = threadIdx.x & (LANES - 1);
    if (gid >= NN) return;
    const uint4* hv = (const uint4*)h;
    float acc[8];
#pragma unroll
    for (int i = 0; i < 8; i++) acc[i] = 0.0f;
    float dinv = g_dinv[gid];
    {
        uint4 u = hv[(long long)gid * LANES + lane];
        acc_u4(acc, u, dinv * dinv);
    }
    int beg = g_rowptr[gid], end = g_rowptr[gid + 1];
    int j = beg;
    for (; j + 3 < end; j += 4) {
        int   s0 = g_csr_src[j],     s1 = g_csr_src[j + 1];
        int   s2 = g_csr_src[j + 2], s3 = g_csr_src[j + 3];
        float c0 = g_csr_coef[j],     c1 = g_csr_coef[j + 1];
        float c2 = g_csr_coef[j + 2], c3 = g_csr_coef[j + 3];
        uint4 v0 = __ldg(&hv[(long long)s0 * LANES + lane]);
        uint4 v1 = __ldg(&hv[(long long)s1 * LANES + lane]);
        uint4 v2 = __ldg(&hv[(long long)s2 * LANES + lane]);
        uint4 v3 = __ldg(&hv[(long long)s3 * LANES + lane]);
        acc_u4(acc, v0, c0);
        acc_u4(acc, v1, c1);
        acc_u4(acc, v2, c2);
        acc_u4(acc, v3, c3);
    }
    for (; j < end; j++) {
        int s = g_csr_src[j];
        float c = g_csr_coef[j];
        uint4 v = __ldg(&hv[(long long)s * LANES + lane]);
        acc_u4(acc, v, c);
    }
    __half2 p0 = __floats2half2_rn(acc[0], acc[1]);
    __half2 p1 = __floats2half2_rn(acc[2], acc[3]);
    __half2 p2 = __floats2half2_rn(acc[4], acc[5]);
    __half2 p3 = __floats2half2_rn(acc[6], acc[7]);
    uint4 r;
    r.x = *(unsigned*)&p0; r.y = *(unsigned*)&p1;
    r.z = *(unsigned*)&p2; r.w = *(unsigned*)&p3;
    ((uint4*)out)[(long long)gid * LANES + lane] = r;
}

// ---------------- fp16 tensor-core GEMM (ldmatrix) ----------------------------
__device__ __forceinline__ unsigned smem_u32(const void* p) {
    return (unsigned)__cvta_generic_to_shared(p);
}

__device__ __forceinline__ void ldsm_x4(unsigned& r0, unsigned& r1, unsigned& r2, unsigned& r3,
                                        unsigned addr) {
    asm volatile("ldmatrix.sync.aligned.m8n8.x4.shared.b16 {%0,%1,%2,%3}, [%4];"
                 : "=r"(r0), "=r"(r1), "=r"(r2), "=r"(r3) : "r"(addr));
}

__device__ __forceinline__ void ldsm_x4_t(unsigned& r0, unsigned& r1, unsigned& r2, unsigned& r3,
                                          unsigned addr) {
    asm volatile("ldmatrix.sync.aligned.m8n8.x4.trans.shared.b16 {%0,%1,%2,%3}, [%4];"
                 : "=r"(r0), "=r"(r1), "=r"(r2), "=r"(r3) : "r"(addr));
}

__device__ __forceinline__ void mma_f16(float* c, const unsigned* a, const unsigned* b) {
    asm volatile(
        "mma.sync.aligned.m16n8k16.row.col.f32.f16.f16.f32 "
        "{%0,%1,%2,%3}, {%4,%5,%6,%7}, {%8,%9}, {%0,%1,%2,%3};"
        : "+f"(c[0]), "+f"(c[1]), "+f"(c[2]), "+f"(c[3])
        : "r"(a[0]), "r"(a[1]), "r"(a[2]), "r"(a[3]), "r"(b[0]), "r"(b[1]));
}

// C[N,M] = A[N,K] @ W[K,M] (+bias,relu). Half in, fp32 accum.
// BM=128, BN=64, BK=32, 256 threads; 8 warps 4x2; warp tile 32x32.
template <int K, int M, bool BIAS_RELU, bool OUTH>
__global__ void __launch_bounds__(256)
hgemm_kernel(const __half* __restrict__ A, const __half* __restrict__ W,
             const float* __restrict__ bias, void* __restrict__ Cv) {
    const int BK = 32;
    __shared__ __align__(16) __half As[128][40];   // stride 40 halves (80B): LDSM conflict-free
    __shared__ __align__(16) __half Bs[32][72];    // row-major [k][n], stride 72 (144B): conflict-free
    const int t = threadIdx.x;
    const int lane = t & 31;
    const int warp = t >> 5;
    const int wm = warp & 3;
    const int wn = warp >> 2;
    const int bm = blockIdx.x * 128;
    const int bn = blockIdx.y * 64;

    float acc[2][4][4];
#pragma unroll
    for (int mi = 0; mi < 2; mi++)
#pragma unroll
        for (int ni = 0; ni < 4; ni++)
#pragma unroll
            for (int r = 0; r < 4; r++) acc[mi][ni][r] = 0.0f;

    for (int k0 = 0; k0 < K; k0 += BK) {
        // stage A: 128 rows x 32 halves = 512 uint4, 2 per thread
#pragma unroll
        for (int r = 0; r < 2; r++) {
            int idx = t + r * 256;
            int row = idx >> 2, c4 = idx & 3;
            uint4 u = make_uint4(0, 0, 0, 0);
            if (bm + row < NN)
                u = *(const uint4*)&A[(long long)(bm + row) * K + k0 + c4 * 8];
            *(uint4*)&As[row][c4 * 8] = u;
        }
        // stage B row-major: 32 k-rows x 64 cols = 256 uint4, 1 per thread
        {
            int kk = t >> 3, c8 = t & 7;
            uint4 u = *(const uint4*)&W[(long long)(k0 + kk) * M + bn + c8 * 8];
            *(uint4*)&Bs[kk][c8 * 8] = u;
        }
        __syncthreads();
#pragma unroll
        for (int ks = 0; ks < 2; ks++) {
            unsigned a[2][4], b[4][2];
            // A: per mi, one ldmatrix.x4 (tiles: m0-7/k0-7, m8-15/k0-7, m0-7/k8-15, m8-15/k8-15)
#pragma unroll
            for (int mi = 0; mi < 2; mi++) {
                int row = wm * 32 + mi * 16 + (lane & 15);
                int col = ks * 16 + (lane >> 4) * 8;
                ldsm_x4(a[mi][0], a[mi][1], a[mi][2], a[mi][3], smem_u32(&As[row][col]));
            }
            // B: per 16-col pair, one ldmatrix.x4.trans from [k][n]
#pragma unroll
            for (int p = 0; p < 2; p++) {
                int row = ks * 16 + ((lane >> 3) & 1) * 8 + (lane & 7);
                int col = wn * 32 + p * 16 + (lane >> 4) * 8;
                ldsm_x4_t(b[2 * p][0], b[2 * p][1], b[2 * p + 1][0], b[2 * p + 1][1],
                          smem_u32(&Bs[row][col]));
            }
#pragma unroll
            for (int mi = 0; mi < 2; mi++)
#pragma unroll
                for (int ni = 0; ni < 4; ni++)
                    mma_f16(acc[mi][ni], a[mi], b[ni]);
        }
        __syncthreads();
    }

    // epilogue
#pragma unroll
    for (int mi = 0; mi < 2; mi++) {
#pragma unroll
        for (int ni = 0; ni < 4; ni++) {
            int col = bn + wn * 32 + ni * 8 + 2 * (lane & 3);
            float bv0 = 0.f, bv1 = 0.f;
            if (BIAS_RELU) { bv0 = bias[col]; bv1 = bias[col + 1]; }
#pragma unroll
            for (int h = 0; h < 2; h++) {
                int row = bm + wm * 32 + mi * 16 + (lane >> 2) + h * 8;
                if (row < NN) {
                    float v0 = acc[mi][ni][2 * h];
                    float v1 = acc[mi][ni][2 * h + 1];
                    if (BIAS_RELU) {
                        v0 = fmaxf(v0 + bv0, 0.0f);
                        v1 = fmaxf(v1 + bv1, 0.0f);
                    }
                    if (OUTH) {
                        __half2 p = __floats2half2_rn(v0, v1);
                        *(__half2*)&((__half*)Cv)[(long long)row * M + col] = p;
                    } else {
                        *(float2*)&((float*)Cv)[(long long)row * M + col] = make_float2(v0, v1);
                    }
                }
            }
        }
    }
}

// ---------------- bias + log_softmax over 40 cols (8 threads/node) ------------
__global__ void softmax40_kernel(const float* __restrict__ P, const float* __restrict__ bias,
                                 float* __restrict__ out, int layer) {
    int gid = blockIdx.x * (blockDim.x >> 3) + (threadIdx.x >> 3);
    int t = threadIdx.x & 7;
    bool valid = gid < NN;
    float v[5];
#pragma unroll
    for (int i = 0; i < 5; i++)
        v[i] = valid ? (P[(long long)gid * 64 + t + 8 * i] + bias[t + 8 * i]) : 0.0f;
    float m = fmaxf(fmaxf(fmaxf(v[0], v[1]), fmaxf(v[2], v[3])), v[4]);
#pragma unroll
    for (int o = 1; o < 8; o <<= 1) m = fmaxf(m, __shfl_xor_sync(0xffffffffu, m, o));
    float s = 0.0f;
#pragma unroll
    for (int i = 0; i < 5; i++) s += expf(v[i] - m);
#pragma unroll
    for (int o = 1; o < 8; o <<= 1) s += __shfl_xor_sync(0xffffffffu, s, o);
    float lse = m + logf(s);
    if (valid) {
        float* op = out + (long long)gid * 160 + layer * 40;
#pragma unroll
        for (int i = 0; i < 5; i++) op[t + 8 * i] = v[i] - lse;
    }
}

// ---------------- last layer: half 40-dim aggregate + bias + log_softmax ------
__global__ void agg40h_kernel(const __half* __restrict__ P, const float* __restrict__ bias,
                              float* __restrict__ out) {
    int gid = blockIdx.x * (blockDim.x >> 3) + (threadIdx.x >> 3);
    int t = threadIdx.x & 7;
    bool valid = gid < NN;
    bool cvalid = t < 5;
    float v[8];
#pragma unroll
    for (int i = 0; i < 8; i++) v[i] = 0.0f;
    const uint4* Pv = (const uint4*)P;   // 8 uint4 per 64-half row
    int beg = 0, end = 0;
    if (valid) {
        float dinv = g_dinv[gid];
        uint4 u = Pv[gid * 8 + t];
        acc_u4(v, u, dinv * dinv);
        beg = g_rowptr[gid];
        end = g_rowptr[gid + 1];
    }
    int j = beg;
    for (; j + 3 < end; j += 4) {
        int   s0 = g_csr_src[j],     s1 = g_csr_src[j + 1];
        int   s2 = g_csr_src[j + 2], s3 = g_csr_src[j + 3];
        float c0 = g_csr_coef[j],     c1 = g_csr_coef[j + 1];
        float c2 = g_csr_coef[j + 2], c3 = g_csr_coef[j + 3];
        uint4 u0 = __ldg(&Pv[s0 * 8 + t]);
        uint4 u1 = __ldg(&Pv[s1 * 8 + t]);
        uint4 u2 = __ldg(&Pv[s2 * 8 + t]);
        uint4 u3 = __ldg(&Pv[s3 * 8 + t]);
        acc_u4(v, u0, c0);
        acc_u4(v, u1, c1);
        acc_u4(v, u2, c2);
        acc_u4(v, u3, c3);
    }
    for (; j < end; j++) {
        int s = g_csr_src[j];
        float c = g_csr_coef[j];
        uint4 u = __ldg(&Pv[s * 8 + t]);
        acc_u4(v, u, c);
    }
    float m = -1e30f;
    if (cvalid) {
#pragma unroll
        for (int i = 0; i < 8; i++) {
            v[i] += bias[8 * t + i];
            m = fmaxf(m, v[i]);
        }
    }
#pragma unroll
    for (int o = 1; o < 8; o <<= 1) m = fmaxf(m, __shfl_xor_sync(0xffffffffu, m, o));
    float s = 0.0f;
    if (cvalid) {
#pragma unroll
        for (int i = 0; i < 8; i++) s += expf(v[i] - m);
    }
#pragma unroll
    for (int o = 1; o < 8; o <<= 1) s += __shfl_xor_sync(0xffffffffu, s, o);
    float lse = m + logf(s);
    if (valid && cvalid) {
        float* op = out + (long long)gid * 160 + 120 + 8 * t;
        *(float4*)&op[0] = make_float4(v[0] - lse, v[1] - lse, v[2] - lse, v[3] - lse);
        *(float4*)&op[4] = make_float4(v[4] - lse, v[5] - lse, v[6] - lse, v[7] - lse);
    }
}

// ---------------- launch -------------------------------------------------------
extern "C" void kernel_launch(void* const* d_in, const int* in_sizes, int n_in,
                              void* d_out, int out_size) {
    const float* x   = (const float*)d_in[0];
    const void*  ei  = d_in[1];
    const float* Wc0 = (const float*)d_in[2];
    const float* bc0 = (const float*)d_in[3];
    const float* Wc1 = (const float*)d_in[4];
    const float* bc1 = (const float*)d_in[5];
    // d_in[6], d_in[7] (Wc2, bc2): dead — final Wc output is never used
    const float* We0 = (const float*)d_in[8];
    const float* be0 = (const float*)d_in[9];
    const float* We1 = (const float*)d_in[10];
    const float* be1 = (const float*)d_in[11];
    const float* We2 = (const float*)d_in[12];
    const float* be2 = (const float*)d_in[13];
    const float* We3 = (const float*)d_in[14];
    const float* be3 = (const float*)d_in[15];
    float* out = (float*)d_out;
    int E = in_sizes[1] / 2;

    float* p64;
    __half *xh, *h1h, *h2h, *h2ah, *h3h, *p64h, *wph, *wc0h, *wc1h;
    cudaGetSymbolAddress((void**)&p64,  g_p64);
    cudaGetSymbolAddress((void**)&xh,   g_xh);
    cudaGetSymbolAddress((void**)&h1h,  g_h1h);
    cudaGetSymbolAddress((void**)&h2h,  g_h2h);
    cudaGetSymbolAddress((void**)&h2ah, g_h2ah);
    cudaGetSymbolAddress((void**)&h3h,  g_h3h);
    cudaGetSymbolAddress((void**)&p64h, g_p64h);
    cudaGetSymbolAddress((void**)&wph,  g_Wph);
    cudaGetSymbolAddress((void**)&wc0h, g_Wc0h);
    cudaGetSymbolAddress((void**)&wc1h, g_Wc1h);
    __half* wp0 = wph;
    __half* wp1 = wph + 1 * 256 * 64;
    __half* wp2 = wph + 2 * 256 * 64;
    __half* wp3 = wph + 3 * 256 * 64;

    static cudaStream_t s1 = nullptr;
    static cudaEvent_t evStart, evPre, evA1, evA2, evS1;
    if (!s1) {
        cudaStreamCreateWithFlags(&s1, cudaStreamNonBlocking);
        cudaEventCreateWithFlags(&evStart, cudaEventDisableTiming);
        cudaEventCreateWithFlags(&evPre,   cudaEventDisableTiming);
        cudaEventCreateWithFlags(&evA1,    cudaEventDisableTiming);
        cudaEventCreateWithFlags(&evA2,    cudaEventDisableTiming);
        cudaEventCreateWithFlags(&evS1,    cudaEventDisableTiming);
    }

    int nb = (NN + 1023) / 1024;
    dim3 g1((NN + 127) / 128, 1);
    dim3 g4((NN + 127) / 128, 4);
    int  gs = (NN + 31) / 32;

    cudaEventRecord(evStart, 0);
    cudaStreamWaitEvent(s1, evStart, 0);

    // s1: converts + weight prep, then layer-0 projection
    convert_half_kernel<<<(NN * 128 / 4 + 255) / 256, 256, 0, s1>>>(x, xh, NN * 128 / 4);
    convert_half_kernel<<<(128 * 256 / 4 + 255) / 256, 256, 0, s1>>>(Wc0, wc0h, 128 * 256 / 4);
    convert_half_kernel<<<(256 * 256 / 4 + 255) / 256, 256, 0, s1>>>(Wc1, wc1h, 256 * 256 / 4);
    pad_wh_kernel<<<(128 * 64 + 255) / 256, 256, 0, s1>>>(We0, wp0, 128);
    pad_wh_kernel<<<(128 * 64 + 255) / 256, 256, 0, s1>>>(We1, wp1, 128);
    pad_wh_kernel<<<(256 * 64 + 255) / 256, 256, 0, s1>>>(We2, wp2, 256);
    pad_wh_kernel<<<(256 * 64 + 255) / 256, 256, 0, s1>>>(We3, wp3, 256);
    cudaEventRecord(evPre, s1);
    hgemm_kernel<128, 64, false, false><<<g1, 256, 0, s1>>>(xh, wp0, nullptr, p64);
    softmax40_kernel<<<gs, 256, 0, s1>>>(p64, be0, out, 0);

    // main: CSR preprocessing (overlaps s1)
    init_kernel<<<(NN + 255) / 256, 256>>>((const int*)ei);
    count_kernel<<<(E + 255) / 256, 256>>>(ei, E);
    scan1_kernel<<<nb, 1024>>>();
    scan2_kernel<<<1, 32>>>(nb);
    scan3_kernel<<<(NN + 255) / 256, 256>>>();
    fill_kernel<<<(E + 255) / 256, 256>>>(ei, E);

    // main chain
    cudaStreamWaitEvent(0, evPre, 0);
    agg_u4_kernel<16><<<(NN * 16 + 255) / 256, 256>>>(xh, h1h);     // D=128
    cudaEventRecord(evA1, 0);
    hgemm_kernel<128, 256, true, true><<<g4, 256>>>(h1h, wc0h, bc0, h2h);
    agg_u4_kernel<32><<<(NN * 32 + 255) / 256, 256>>>(h2h, h2ah);   // D=256
    cudaEventRecord(evA2, 0);
    hgemm_kernel<256, 256, true, true><<<g4, 256>>>(h2ah, wc1h, bc1, h3h);
    hgemm_kernel<256, 64, false, true><<<g1, 256>>>(h3h, wp3, nullptr, p64h);
    agg40h_kernel<<<gs, 256>>>(p64h, be3, out);

    // s1: per-layer projections overlap the Wc GEMMs / aggs
    cudaStreamWaitEvent(s1, evA1, 0);
    hgemm_kernel<128, 64, false, false><<<g1, 256, 0, s1>>>(h1h, wp1, nullptr, p64);
    softmax40_kernel<<<gs, 256, 0, s1>>>(p64, be1, out, 1);
    cudaStreamWaitEvent(s1, evA2, 0);
    hgemm_kernel<256, 64, false, false><<<g1, 256, 0, s1>>>(h2ah, wp2, nullptr, p64);
    softmax40_kernel<<<gs, 256, 0, s1>>>(p64, be2, out, 2);
    cudaEventRecord(evS1, s1);

    cudaStreamWaitEvent(0, evS1, 0);
}

// round 6
// speedup vs baseline: 2.9197x; 1.0359x over previous
#include <cuda_runtime.h>
#include <cuda_fp16.h>
#include <math.h>

#define NN 100000
#define EE 1600000

// ---------------- scratch (static device globals; no allocs allowed) ----------
__device__ __half g_xh[NN * 128];
__device__ __half g_h1h[NN * 128];
__device__ __half g_h2h[NN * 256];
__device__ __half g_h2ah[NN * 256];
__device__ __half g_h3h[NN * 256];
__device__ __half g_p64h[NN * 64];
__device__ float  g_dinv[NN];
__device__ int    g_deg[NN];
__device__ int    g_rowptr[NN + 1];
__device__ int    g_cursor[NN];
__device__ int2   g_csr[EE];            // (src, coef bits) interleaved
__device__ int    g_blksum[128];
__device__ int    g_blkoff[128];
__device__ int    g_is64;
__device__ __half g_Wph[4 * 256 * 64];
__device__ __half g_Wc0h[128 * 256];
__device__ __half g_Wc1h[256 * 256];

// ---------------- edge index dtype handling ----------------------------------
__device__ __forceinline__ int edge_at(const void* ei, long long idx) {
    if (g_is64) return (int)((const long long*)ei)[idx];
    return ((const int*)ei)[idx];
}

__global__ void init_kernel(const int* ei32) {
    int i = blockIdx.x * blockDim.x + threadIdx.x;
    if (i < NN) g_deg[i] = 0;
    if (blockIdx.x == 0 && threadIdx.x == 0) {
        int nz = 0;
        for (int k = 0; k < 64; k++) nz |= ei32[2 * k + 1];
        g_is64 = (nz == 0) ? 1 : 0;   // int64 LE: hi-words all zero
    }
}

__global__ void count_kernel(const void* ei, int E) {
    int e = blockIdx.x * blockDim.x + threadIdx.x;
    if (e >= E) return;
    int d = edge_at(ei, (long long)E + e);
    atomicAdd(&g_deg[d], 1);
}

__global__ void scan1_kernel() {
    __shared__ int s[1024];
    int t = threadIdx.x;
    int idx = blockIdx.x * 1024 + t;
    int v = (idx < NN) ? g_deg[idx] : 0;
    if (idx < NN) g_dinv[idx] = rsqrtf((float)v + 1.0f);
    s[t] = v;
    __syncthreads();
    for (int o = 1; o < 1024; o <<= 1) {
        int x = (t >= o) ? s[t - o] : 0;
        __syncthreads();
        s[t] += x;
        __syncthreads();
    }
    if (idx < NN) g_rowptr[idx] = s[t] - v;
    if (t == 1023) g_blksum[blockIdx.x] = s[t];
}

// warp-parallel scan over block sums (nb <= 128)
__global__ void scan2_kernel(int nb) {
    int t = threadIdx.x;   // 32 threads
    int idx0 = t * 4;
    int loc[4];
    int sum = 0;
#pragma unroll
    for (int k = 0; k < 4; k++) {
        int i = idx0 + k;
        int x = (i < nb) ? g_blksum[i] : 0;
        loc[k] = sum;
        sum += x;
    }
    int pre = sum;
#pragma unroll
    for (int o = 1; o < 32; o <<= 1) {
        int y = __shfl_up_sync(0xffffffffu, pre, o);
        if (t >= o) pre += y;
    }
    int excl = pre - sum;
#pragma unroll
    for (int k = 0; k < 4; k++) {
        int i = idx0 + k;
        if (i < nb) g_blkoff[i] = excl + loc[k];
    }
    if (t == 31) g_rowptr[NN] = excl + sum;
}

__global__ void scan3_kernel() {
    int i = blockIdx.x * blockDim.x + threadIdx.x;
    if (i < NN) {
        int r = g_rowptr[i] + g_blkoff[i >> 10];
        g_rowptr[i] = r;
        g_cursor[i] = r;
    }
}

__global__ void fill_kernel(const void* ei, int E) {
    int e = blockIdx.x * blockDim.x + threadIdx.x;
    if (e >= E) return;
    int s = edge_at(ei, e);
    int d = edge_at(ei, (long long)E + e);
    int pos = atomicAdd(&g_cursor[d], 1);
    g_csr[pos] = make_int2(s, __float_as_int(g_dinv[s] * g_dinv[d]));
}

// ---------------- one-shot prep: x->half, Wc converts, proj pads ---------------
// block ranges: [0,12500) x | [,+32) Wc0 | [,+64) Wc1 | pads 32/32/64/64
__global__ void prep_all_kernel(const float* __restrict__ x,
                                const float* __restrict__ Wc0, const float* __restrict__ Wc1,
                                const float* __restrict__ We0, const float* __restrict__ We1,
                                const float* __restrict__ We2, const float* __restrict__ We3) {
    int b = blockIdx.x;
    int t = threadIdx.x;
    if (b < 12500) {                       // x: 3.2M float4
        int i = b * 256 + t;
        float4 v = *(const float4*)&x[i * 4];
        __half2 a = __floats2half2_rn(v.x, v.y);
        __half2 c = __floats2half2_rn(v.z, v.w);
        uint2 u; u.x = *(unsigned*)&a; u.y = *(unsigned*)&c;
        *(uint2*)&g_xh[i * 4] = u;
        return;
    }
    b -= 12500;
    if (b < 32) {                          // Wc0: 8192 float4
        int i = b * 256 + t;
        float4 v = *(const float4*)&Wc0[i * 4];
        __half2 a = __floats2half2_rn(v.x, v.y);
        __half2 c = __floats2half2_rn(v.z, v.w);
        uint2 u; u.x = *(unsigned*)&a; u.y = *(unsigned*)&c;
        *(uint2*)&g_Wc0h[i * 4] = u;
        return;
    }
    b -= 32;
    if (b < 64) {                          // Wc1: 16384 float4
        int i = b * 256 + t;
        float4 v = *(const float4*)&Wc1[i * 4];
        __half2 a = __floats2half2_rn(v.x, v.y);
        __half2 c = __floats2half2_rn(v.z, v.w);
        uint2 u; u.x = *(unsigned*)&a; u.y = *(unsigned*)&c;
        *(uint2*)&g_Wc1h[i * 4] = u;
        return;
    }
    b -= 64;
    const float* Ws[4] = {We0, We1, We2, We3};
    const int   nblk[4] = {32, 32, 64, 64};
    for (int w = 0; w < 4; w++) {
        if (b < nblk[w]) {
            int idx = b * 256 + t;         // element index into K*64
            int k = idx >> 6, j = idx & 63;
            g_Wph[w * 256 * 64 + idx] = __float2half((j < 40) ? Ws[w][k * 40 + j] : 0.0f);
            return;
        }
        b -= nblk[w];
    }
}

// ---------------- half accumulate helpers --------------------------------------
__device__ __forceinline__ void acc_u2(float* a, unsigned lo, unsigned hi, float c) {
    float2 f0 = __half22float2(*reinterpret_cast<__half2*>(&lo));
    float2 f1 = __half22float2(*reinterpret_cast<__half2*>(&hi));
    a[0] = fmaf(c, f0.x, a[0]);
    a[1] = fmaf(c, f0.y, a[1]);
    a[2] = fmaf(c, f1.x, a[2]);
    a[3] = fmaf(c, f1.y, a[3]);
}

__device__ __forceinline__ void acc_u4(float* a, uint4 u, float c) {
    acc_u2(a,     u.x, u.y, c);
    acc_u2(a + 4, u.z, u.w, c);
}

// ---------------- aggregation: LANES lanes/node, uint4 gather, 4-edge pipe ----
template <int LANES>
__global__ void agg_u4_kernel(const __half* __restrict__ h, __half* __restrict__ out) {
    int gid  = (blockIdx.x * blockDim.x + threadIdx.x) / LANES;
    int lane = threadIdx.x & (LANES - 1);
    if (gid >= NN) return;
    const uint4* hv = (const uint4*)h;
    float acc[8];
#pragma unroll
    for (int i = 0; i < 8; i++) acc[i] = 0.0f;
    float dinv = g_dinv[gid];
    {
        uint4 u = hv[(long long)gid * LANES + lane];
        acc_u4(acc, u, dinv * dinv);
    }
    int beg = g_rowptr[gid], end = g_rowptr[gid + 1];
    int j = beg;
    for (; j + 3 < end; j += 4) {
        int2 e0 = g_csr[j],     e1 = g_csr[j + 1];
        int2 e2 = g_csr[j + 2], e3 = g_csr[j + 3];
        uint4 v0 = __ldg(&hv[(long long)e0.x * LANES + lane]);
        uint4 v1 = __ldg(&hv[(long long)e1.x * LANES + lane]);
        uint4 v2 = __ldg(&hv[(long long)e2.x * LANES + lane]);
        uint4 v3 = __ldg(&hv[(long long)e3.x * LANES + lane]);
        acc_u4(acc, v0, __int_as_float(e0.y));
        acc_u4(acc, v1, __int_as_float(e1.y));
        acc_u4(acc, v2, __int_as_float(e2.y));
        acc_u4(acc, v3, __int_as_float(e3.y));
    }
    for (; j < end; j++) {
        int2 e = g_csr[j];
        uint4 v = __ldg(&hv[(long long)e.x * LANES + lane]);
        acc_u4(acc, v, __int_as_float(e.y));
    }
    __half2 p0 = __floats2half2_rn(acc[0], acc[1]);
    __half2 p1 = __floats2half2_rn(acc[2], acc[3]);
    __half2 p2 = __floats2half2_rn(acc[4], acc[5]);
    __half2 p3 = __floats2half2_rn(acc[6], acc[7]);
    uint4 r;
    r.x = *(unsigned*)&p0; r.y = *(unsigned*)&p1;
    r.z = *(unsigned*)&p2; r.w = *(unsigned*)&p3;
    ((uint4*)out)[(long long)gid * LANES + lane] = r;
}

// ---------------- fp16 tensor-core GEMM (ldmatrix) ----------------------------
__device__ __forceinline__ unsigned smem_u32(const void* p) {
    return (unsigned)__cvta_generic_to_shared(p);
}

__device__ __forceinline__ void ldsm_x4(unsigned& r0, unsigned& r1, unsigned& r2, unsigned& r3,
                                        unsigned addr) {
    asm volatile("ldmatrix.sync.aligned.m8n8.x4.shared.b16 {%0,%1,%2,%3}, [%4];"
                 : "=r"(r0), "=r"(r1), "=r"(r2), "=r"(r3) : "r"(addr));
}

__device__ __forceinline__ void ldsm_x4_t(unsigned& r0, unsigned& r1, unsigned& r2, unsigned& r3,
                                          unsigned addr) {
    asm volatile("ldmatrix.sync.aligned.m8n8.x4.trans.shared.b16 {%0,%1,%2,%3}, [%4];"
                 : "=r"(r0), "=r"(r1), "=r"(r2), "=r"(r3) : "r"(addr));
}

__device__ __forceinline__ void mma_f16(float* c, const unsigned* a, const unsigned* b) {
    asm volatile(
        "mma.sync.aligned.m16n8k16.row.col.f32.f16.f16.f32 "
        "{%0,%1,%2,%3}, {%4,%5,%6,%7}, {%8,%9}, {%0,%1,%2,%3};"
        : "+f"(c[0]), "+f"(c[1]), "+f"(c[2]), "+f"(c[3])
        : "r"(a[0]), "r"(a[1]), "r"(a[2]), "r"(a[3]), "r"(b[0]), "r"(b[1]));
}

// C[N,M] = A[N,K] @ W[K,M]. Half in, fp32 accum. BM=128, BN=64, BK=32, 256 thr.
// SMAX: fused bias + row log_softmax (cols 0..39) written straight to out[.,layer,.]
template <int K, int M, bool BIAS_RELU, bool OUTH, bool SMAX>
__global__ void __launch_bounds__(256)
hgemm_kernel(const __half* __restrict__ A, const __half* __restrict__ W,
             const float* __restrict__ bias, void* __restrict__ Cv,
             float* __restrict__ out, int layer) {
    const int BK = 32;
    constexpr int AS_BYTES = 128 * 40 * 2;          // 10240
    constexpr int SMEM_BYTES = SMAX ? (128 * 66 * 4) : (AS_BYTES + 32 * 72 * 2);
    __shared__ __align__(16) unsigned char smemraw[SMEM_BYTES];
    __half (*As)[40] = reinterpret_cast<__half(*)[40]>(smemraw);
    __half (*Bs)[72] = reinterpret_cast<__half(*)[72]>(smemraw + AS_BYTES);
    float  (*ps)[66] = reinterpret_cast<float(*)[66]>(smemraw);

    const int t = threadIdx.x;
    const int lane = t & 31;
    const int warp = t >> 5;
    const int wm = warp & 3;
    const int wn = warp >> 2;
    const int bm = blockIdx.x * 128;
    const int bn = blockIdx.y * 64;

    float acc[2][4][4];
#pragma unroll
    for (int mi = 0; mi < 2; mi++)
#pragma unroll
        for (int ni = 0; ni < 4; ni++)
#pragma unroll
            for (int r = 0; r < 4; r++) acc[mi][ni][r] = 0.0f;

    for (int k0 = 0; k0 < K; k0 += BK) {
#pragma unroll
        for (int r = 0; r < 2; r++) {
            int idx = t + r * 256;
            int row = idx >> 2, c4 = idx & 3;
            uint4 u = make_uint4(0, 0, 0, 0);
            if (bm + row < NN)
                u = *(const uint4*)&A[(long long)(bm + row) * K + k0 + c4 * 8];
            *(uint4*)&As[row][c4 * 8] = u;
        }
        {
            int kk = t >> 3, c8 = t & 7;
            uint4 u = *(const uint4*)&W[(long long)(k0 + kk) * M + bn + c8 * 8];
            *(uint4*)&Bs[kk][c8 * 8] = u;
        }
        __syncthreads();
#pragma unroll
        for (int ks = 0; ks < 2; ks++) {
            unsigned a[2][4], b[4][2];
#pragma unroll
            for (int mi = 0; mi < 2; mi++) {
                int row = wm * 32 + mi * 16 + (lane & 15);
                int col = ks * 16 + (lane >> 4) * 8;
                ldsm_x4(a[mi][0], a[mi][1], a[mi][2], a[mi][3], smem_u32(&As[row][col]));
            }
#pragma unroll
            for (int p = 0; p < 2; p++) {
                int row = ks * 16 + ((lane >> 3) & 1) * 8 + (lane & 7);
                int col = wn * 32 + p * 16 + (lane >> 4) * 8;
                ldsm_x4_t(b[2 * p][0], b[2 * p][1], b[2 * p + 1][0], b[2 * p + 1][1],
                          smem_u32(&Bs[row][col]));
            }
#pragma unroll
            for (int mi = 0; mi < 2; mi++)
#pragma unroll
                for (int ni = 0; ni < 4; ni++)
                    mma_f16(acc[mi][ni], a[mi], b[ni]);
        }
        __syncthreads();
    }

    if (SMAX) {
        // stage accumulators to smem (cols 40..63 garbage; never read)
#pragma unroll
        for (int mi = 0; mi < 2; mi++)
#pragma unroll
            for (int ni = 0; ni < 4; ni++) {
                int col = wn * 32 + ni * 8 + 2 * (lane & 3);
#pragma unroll
                for (int h = 0; h < 2; h++) {
                    int row = wm * 32 + mi * 16 + (lane >> 2) + h * 8;
                    *(float2*)&ps[row][col] =
                        make_float2(acc[mi][ni][2 * h], acc[mi][ni][2 * h + 1]);
                }
            }
        __syncthreads();
        // row log-softmax: 8-lane groups, 4 passes of 32 rows
        int gi = t >> 3, sub = t & 7;
#pragma unroll
        for (int pass = 0; pass < 4; pass++) {
            int r = pass * 32 + gi;
            int grow = bm + r;
            float v[5];
#pragma unroll
            for (int i = 0; i < 5; i++) v[i] = ps[r][sub + 8 * i] + bias[sub + 8 * i];
            float m = fmaxf(fmaxf(fmaxf(v[0], v[1]), fmaxf(v[2], v[3])), v[4]);
#pragma unroll
            for (int o = 1; o < 8; o <<= 1) m = fmaxf(m, __shfl_xor_sync(0xffffffffu, m, o));
            float s = 0.0f;
#pragma unroll
            for (int i = 0; i < 5; i++) s += expf(v[i] - m);
#pragma unroll
            for (int o = 1; o < 8; o <<= 1) s += __shfl_xor_sync(0xffffffffu, s, o);
            float lse = m + logf(s);
            if (grow < NN) {
                float* op = out + (long long)grow * 160 + layer * 40;
#pragma unroll
                for (int i = 0; i < 5; i++) op[sub + 8 * i] = v[i] - lse;
            }
        }
    } else {
#pragma unroll
        for (int mi = 0; mi < 2; mi++) {
#pragma unroll
            for (int ni = 0; ni < 4; ni++) {
                int col = bn + wn * 32 + ni * 8 + 2 * (lane & 3);
                float bv0 = 0.f, bv1 = 0.f;
                if (BIAS_RELU) { bv0 = bias[col]; bv1 = bias[col + 1]; }
#pragma unroll
                for (int h = 0; h < 2; h++) {
                    int row = bm + wm * 32 + mi * 16 + (lane >> 2) + h * 8;
                    if (row < NN) {
                        float v0 = acc[mi][ni][2 * h];
                        float v1 = acc[mi][ni][2 * h + 1];
                        if (BIAS_RELU) {
                            v0 = fmaxf(v0 + bv0, 0.0f);
                            v1 = fmaxf(v1 + bv1, 0.0f);
                        }
                        if (OUTH) {
                            __half2 p = __floats2half2_rn(v0, v1);
                            *(__half2*)&((__half*)Cv)[(long long)row * M + col] = p;
                        } else {
                            *(float2*)&((float*)Cv)[(long long)row * M + col] = make_float2(v0, v1);
                        }
                    }
                }
            }
        }
    }
}

// ---------------- last layer: half 40-dim aggregate + bias + log_softmax ------
__global__ void agg40h_kernel(const __half* __restrict__ P, const float* __restrict__ bias,
                              float* __restrict__ out) {
    int gid = blockIdx.x * (blockDim.x >> 3) + (threadIdx.x >> 3);
    int t = threadIdx.x & 7;
    bool valid = gid < NN;
    bool cvalid = t < 5;
    float v[8];
#pragma unroll
    for (int i = 0; i < 8; i++) v[i] = 0.0f;
    const uint4* Pv = (const uint4*)P;
    int beg = 0, end = 0;
    if (valid) {
        float dinv = g_dinv[gid];
        uint4 u = Pv[gid * 8 + t];
        acc_u4(v, u, dinv * dinv);
        beg = g_rowptr[gid];
        end = g_rowptr[gid + 1];
    }
    int j = beg;
    for (; j + 3 < end; j += 4) {
        int2 e0 = g_csr[j],     e1 = g_csr[j + 1];
        int2 e2 = g_csr[j + 2], e3 = g_csr[j + 3];
        uint4 u0 = __ldg(&Pv[e0.x * 8 + t]);
        uint4 u1 = __ldg(&Pv[e1.x * 8 + t]);
        uint4 u2 = __ldg(&Pv[e2.x * 8 + t]);
        uint4 u3 = __ldg(&Pv[e3.x * 8 + t]);
        acc_u4(v, u0, __int_as_float(e0.y));
        acc_u4(v, u1, __int_as_float(e1.y));
        acc_u4(v, u2, __int_as_float(e2.y));
        acc_u4(v, u3, __int_as_float(e3.y));
    }
    for (; j < end; j++) {
        int2 e = g_csr[j];
        uint4 u = __ldg(&Pv[e.x * 8 + t]);
        acc_u4(v, u, __int_as_float(e.y));
    }
    float m = -1e30f;
    if (cvalid) {
#pragma unroll
        for (int i = 0; i < 8; i++) {
            v[i] += bias[8 * t + i];
            m = fmaxf(m, v[i]);
        }
    }
#pragma unroll
    for (int o = 1; o < 8; o <<= 1) m = fmaxf(m, __shfl_xor_sync(0xffffffffu, m, o));
    float s = 0.0f;
    if (cvalid) {
#pragma unroll
        for (int i = 0; i < 8; i++) s += expf(v[i] - m);
    }
#pragma unroll
    for (int o = 1; o < 8; o <<= 1) s += __shfl_xor_sync(0xffffffffu, s, o);
    float lse = m + logf(s);
    if (valid && cvalid) {
        float* op = out + (long long)gid * 160 + 120 + 8 * t;
        *(float4*)&op[0] = make_float4(v[0] - lse, v[1] - lse, v[2] - lse, v[3] - lse);
        *(float4*)&op[4] = make_float4(v[4] - lse, v[5] - lse, v[6] - lse, v[7] - lse);
    }
}

// ---------------- launch -------------------------------------------------------
extern "C" void kernel_launch(void* const* d_in, const int* in_sizes, int n_in,
                              void* d_out, int out_size) {
    const float* x   = (const float*)d_in[0];
    const void*  ei  = d_in[1];
    const float* Wc0 = (const float*)d_in[2];
    const float* bc0 = (const float*)d_in[3];
    const float* Wc1 = (const float*)d_in[4];
    const float* bc1 = (const float*)d_in[5];
    // d_in[6], d_in[7] (Wc2, bc2): dead — final Wc output is never used
    const float* We0 = (const float*)d_in[8];
    const float* be0 = (const float*)d_in[9];
    const float* We1 = (const float*)d_in[10];
    const float* be1 = (const float*)d_in[11];
    const float* We2 = (const float*)d_in[12];
    const float* be2 = (const float*)d_in[13];
    const float* We3 = (const float*)d_in[14];
    const float* be3 = (const float*)d_in[15];
    float* out = (float*)d_out;
    int E = in_sizes[1] / 2;

    __half *xh, *h1h, *h2h, *h2ah, *h3h, *p64h, *wph, *wc0h, *wc1h;
    cudaGetSymbolAddress((void**)&xh,   g_xh);
    cudaGetSymbolAddress((void**)&h1h,  g_h1h);
    cudaGetSymbolAddress((void**)&h2h,  g_h2h);
    cudaGetSymbolAddress((void**)&h2ah, g_h2ah);
    cudaGetSymbolAddress((void**)&h3h,  g_h3h);
    cudaGetSymbolAddress((void**)&p64h, g_p64h);
    cudaGetSymbolAddress((void**)&wph,  g_Wph);
    cudaGetSymbolAddress((void**)&wc0h, g_Wc0h);
    cudaGetSymbolAddress((void**)&wc1h, g_Wc1h);
    __half* wp0 = wph;
    __half* wp1 = wph + 1 * 256 * 64;
    __half* wp2 = wph + 2 * 256 * 64;
    __half* wp3 = wph + 3 * 256 * 64;

    static cudaStream_t s1 = nullptr;
    static cudaEvent_t evStart, evPre, evA1, evA2, evS1;
    if (!s1) {
        cudaStreamCreateWithFlags(&s1, cudaStreamNonBlocking);
        cudaEventCreateWithFlags(&evStart, cudaEventDisableTiming);
        cudaEventCreateWithFlags(&evPre,   cudaEventDisableTiming);
        cudaEventCreateWithFlags(&evA1,    cudaEventDisableTiming);
        cudaEventCreateWithFlags(&evA2,    cudaEventDisableTiming);
        cudaEventCreateWithFlags(&evS1,    cudaEventDisableTiming);
    }

    int nb = (NN + 1023) / 1024;
    dim3 g1((NN + 127) / 128, 1);
    dim3 g4((NN + 127) / 128, 4);
    int  gs = (NN + 31) / 32;

    cudaEventRecord(evStart, 0);
    cudaStreamWaitEvent(s1, evStart, 0);

    // s1: all weight/feature prep in ONE kernel, then fused layer-0 projection
    prep_all_kernel<<<12788, 256, 0, s1>>>(x, Wc0, Wc1, We0, We1, We2, We3);
    cudaEventRecord(evPre, s1);
    hgemm_kernel<128, 64, false, false, true><<<g1, 256, 0, s1>>>(xh, wp0, be0, nullptr, out, 0);

    // main: CSR preprocessing (overlaps s1)
    init_kernel<<<(NN + 255) / 256, 256>>>((const int*)ei);
    count_kernel<<<(E + 255) / 256, 256>>>(ei, E);
    scan1_kernel<<<nb, 1024>>>();
    scan2_kernel<<<1, 32>>>(nb);
    scan3_kernel<<<(NN + 255) / 256, 256>>>();
    fill_kernel<<<(E + 255) / 256, 256>>>(ei, E);

    // main chain
    cudaStreamWaitEvent(0, evPre, 0);
    agg_u4_kernel<16><<<(NN * 16 + 255) / 256, 256>>>(xh, h1h);     // D=128
    cudaEventRecord(evA1, 0);
    hgemm_kernel<128, 256, true, true, false><<<g4, 256>>>(h1h, wc0h, bc0, h2h, nullptr, 0);
    agg_u4_kernel<32><<<(NN * 32 + 255) / 256, 256>>>(h2h, h2ah);   // D=256
    cudaEventRecord(evA2, 0);
    hgemm_kernel<256, 256, true, true, false><<<g4, 256>>>(h2ah, wc1h, bc1, h3h, nullptr, 0);
    hgemm_kernel<256, 64, false, true, false><<<g1, 256>>>(h3h, wp3, nullptr, p64h, nullptr, 0);
    agg40h_kernel<<<gs, 256>>>(p64h, be3, out);

    // s1: fused projection layers 1/2 overlap the Wc GEMMs / aggs
    cudaStreamWaitEvent(s1, evA1, 0);
    hgemm_kernel<128, 64, false, false, true><<<g1, 256, 0, s1>>>(h1h, wp1, be1, nullptr, out, 1);
    cudaStreamWaitEvent(s1, evA2, 0);
    hgemm_kernel<256, 64, false, false, true><<<g1, 256, 0, s1>>>(h2ah, wp2, be2, nullptr, out, 2);
    cudaEventRecord(evS1, s1);

    cudaStreamWaitEvent(0, evS1, 0);
}

// round 7
// speedup vs baseline: 3.3172x; 1.1361x over previous
#include <cuda_runtime.h>
#include <cuda_fp16.h>
#include <math.h>

#define NN 100000
#define EE 1600000

// ---------------- scratch (static device globals; no allocs allowed) ----------
__device__ __half g_xh[NN * 128];
__device__ __half g_h1h[NN * 128];
__device__ __half g_h2h[NN * 256];
__device__ __half g_h2ah[NN * 256];
__device__ __half g_h3h[NN * 256];
__device__ __half g_p64h[NN * 64];
__device__ float  g_dinv[NN];
__device__ int    g_deg[NN];
__device__ int    g_rowptr[NN + 1];
__device__ int    g_cursor[NN];
__device__ int    g_csr[EE];            // src only; coef derived from g_dinv
__device__ int    g_blksum[128];
__device__ int    g_is64;
__device__ __half g_Wph[4 * 256 * 64];
__device__ __half g_Wc0h[128 * 256];
__device__ __half g_Wc1h[256 * 256];

// ---------------- edge index dtype handling ----------------------------------
__device__ __forceinline__ int edge_at(const void* ei, long long idx) {
    if (g_is64) return (int)((const long long*)ei)[idx];
    return ((const int*)ei)[idx];
}

__global__ void init_kernel(const int* ei32) {
    int i = blockIdx.x * blockDim.x + threadIdx.x;
    if (i < NN) g_deg[i] = 0;
    if (blockIdx.x == 0 && threadIdx.x == 0) {
        int nz = 0;
        for (int k = 0; k < 64; k++) nz |= ei32[2 * k + 1];
        g_is64 = (nz == 0) ? 1 : 0;   // int64 LE: hi-words all zero
    }
}

__global__ void count_kernel(const void* ei, int E) {
    int e = blockIdx.x * blockDim.x + threadIdx.x;
    if (e >= E) return;
    int d = edge_at(ei, (long long)E + e);
    atomicAdd(&g_deg[d], 1);
}

__global__ void scan1_kernel() {
    __shared__ int s[1024];
    int t = threadIdx.x;
    int idx = blockIdx.x * 1024 + t;
    int v = (idx < NN) ? g_deg[idx] : 0;
    if (idx < NN) g_dinv[idx] = rsqrtf((float)v + 1.0f);
    s[t] = v;
    __syncthreads();
    for (int o = 1; o < 1024; o <<= 1) {
        int x = (t >= o) ? s[t - o] : 0;
        __syncthreads();
        s[t] += x;
        __syncthreads();
    }
    if (idx < NN) g_rowptr[idx] = s[t] - v;
    if (t == 1023) g_blksum[blockIdx.x] = s[t];
}

// merged scan2+scan3: every block redundantly scans the <=128 block sums
__global__ void scan23_kernel(int nb) {
    __shared__ int boff[128];
    __shared__ int btot;
    int t = threadIdx.x;
    if (t < 32) {
        int loc[4];
        int sum = 0;
#pragma unroll
        for (int k = 0; k < 4; k++) {
            int i = t * 4 + k;
            int x = (i < nb) ? g_blksum[i] : 0;
            loc[k] = sum;
            sum += x;
        }
        int pre = sum;
#pragma unroll
        for (int o = 1; o < 32; o <<= 1) {
            int y = __shfl_up_sync(0xffffffffu, pre, o);
            if (t >= o) pre += y;
        }
        int excl = pre - sum;
#pragma unroll
        for (int k = 0; k < 4; k++) boff[t * 4 + k] = excl + loc[k];
        if (t == 31) btot = excl + sum;
    }
    __syncthreads();
    int i = blockIdx.x * blockDim.x + t;
    if (i < NN) {
        int r = g_rowptr[i] + boff[i >> 10];
        g_rowptr[i] = r;
        g_cursor[i] = r;
    }
    if (blockIdx.x == 0 && t == 0) g_rowptr[NN] = btot;
}

__global__ void fill_kernel(const void* ei, int E) {
    int e = blockIdx.x * blockDim.x + threadIdx.x;
    if (e >= E) return;
    int s = edge_at(ei, e);
    int d = edge_at(ei, (long long)E + e);
    int pos = atomicAdd(&g_cursor[d], 1);
    g_csr[pos] = s;
}

// ---------------- one-shot prep: x->half, Wc converts, proj pads ---------------
__global__ void prep_all_kernel(const float* __restrict__ x,
                                const float* __restrict__ Wc0, const float* __restrict__ Wc1,
                                const float* __restrict__ We0, const float* __restrict__ We1,
                                const float* __restrict__ We2, const float* __restrict__ We3) {
    int b = blockIdx.x;
    int t = threadIdx.x;
    if (b < 12500) {
        int i = b * 256 + t;
        float4 v = *(const float4*)&x[i * 4];
        __half2 a = __floats2half2_rn(v.x, v.y);
        __half2 c = __floats2half2_rn(v.z, v.w);
        uint2 u; u.x = *(unsigned*)&a; u.y = *(unsigned*)&c;
        *(uint2*)&g_xh[i * 4] = u;
        return;
    }
    b -= 12500;
    if (b < 32) {
        int i = b * 256 + t;
        float4 v = *(const float4*)&Wc0[i * 4];
        __half2 a = __floats2half2_rn(v.x, v.y);
        __half2 c = __floats2half2_rn(v.z, v.w);
        uint2 u; u.x = *(unsigned*)&a; u.y = *(unsigned*)&c;
        *(uint2*)&g_Wc0h[i * 4] = u;
        return;
    }
    b -= 32;
    if (b < 64) {
        int i = b * 256 + t;
        float4 v = *(const float4*)&Wc1[i * 4];
        __half2 a = __floats2half2_rn(v.x, v.y);
        __half2 c = __floats2half2_rn(v.z, v.w);
        uint2 u; u.x = *(unsigned*)&a; u.y = *(unsigned*)&c;
        *(uint2*)&g_Wc1h[i * 4] = u;
        return;
    }
    b -= 64;
    const float* Ws[4] = {We0, We1, We2, We3};
    const int   nblk[4] = {32, 32, 64, 64};
    for (int w = 0; w < 4; w++) {
        if (b < nblk[w]) {
            int idx = b * 256 + t;
            int k = idx >> 6, j = idx & 63;
            g_Wph[w * 256 * 64 + idx] = __float2half((j < 40) ? Ws[w][k * 40 + j] : 0.0f);
            return;
        }
        b -= nblk[w];
    }
}

// ---------------- half accumulate helpers --------------------------------------
__device__ __forceinline__ void acc_u2(float* a, unsigned lo, unsigned hi, float c) {
    float2 f0 = __half22float2(*reinterpret_cast<__half2*>(&lo));
    float2 f1 = __half22float2(*reinterpret_cast<__half2*>(&hi));
    a[0] = fmaf(c, f0.x, a[0]);
    a[1] = fmaf(c, f0.y, a[1]);
    a[2] = fmaf(c, f1.x, a[2]);
    a[3] = fmaf(c, f1.y, a[3]);
}

__device__ __forceinline__ void acc_u4(float* a, uint4 u, float c) {
    acc_u2(a,     u.x, u.y, c);
    acc_u2(a + 4, u.z, u.w, c);
}

// ---------------- aggregation: LANES lanes/node, uint4 gather, 4-edge pipe ----
// out_row(gid) = dinv[gid] * ( dinv[gid]*h[gid] + sum_e dinv[src_e]*h[src_e] )
template <int LANES>
__global__ void agg_u4_kernel(const __half* __restrict__ h, __half* __restrict__ out) {
    int gid  = (blockIdx.x * blockDim.x + threadIdx.x) / LANES;
    int lane = threadIdx.x & (LANES - 1);
    if (gid >= NN) return;
    const uint4* hv = (const uint4*)h;
    float acc[8];
#pragma unroll
    for (int i = 0; i < 8; i++) acc[i] = 0.0f;
    float dinv0 = g_dinv[gid];
    {
        uint4 u = hv[(long long)gid * LANES + lane];
        acc_u4(acc, u, dinv0);
    }
    int beg = g_rowptr[gid], end = g_rowptr[gid + 1];
    int j = beg;
    for (; j + 3 < end; j += 4) {
        int s0 = g_csr[j],     s1 = g_csr[j + 1];
        int s2 = g_csr[j + 2], s3 = g_csr[j + 3];
        float c0 = __ldg(&g_dinv[s0]);
        float c1 = __ldg(&g_dinv[s1]);
        float c2 = __ldg(&g_dinv[s2]);
        float c3 = __ldg(&g_dinv[s3]);
        uint4 v0 = __ldg(&hv[(long long)s0 * LANES + lane]);
        uint4 v1 = __ldg(&hv[(long long)s1 * LANES + lane]);
        uint4 v2 = __ldg(&hv[(long long)s2 * LANES + lane]);
        uint4 v3 = __ldg(&hv[(long long)s3 * LANES + lane]);
        acc_u4(acc, v0, c0);
        acc_u4(acc, v1, c1);
        acc_u4(acc, v2, c2);
        acc_u4(acc, v3, c3);
    }
    for (; j < end; j++) {
        int s = g_csr[j];
        float c = __ldg(&g_dinv[s]);
        uint4 v = __ldg(&hv[(long long)s * LANES + lane]);
        acc_u4(acc, v, c);
    }
    __half2 p0 = __floats2half2_rn(acc[0] * dinv0, acc[1] * dinv0);
    __half2 p1 = __floats2half2_rn(acc[2] * dinv0, acc[3] * dinv0);
    __half2 p2 = __floats2half2_rn(acc[4] * dinv0, acc[5] * dinv0);
    __half2 p3 = __floats2half2_rn(acc[6] * dinv0, acc[7] * dinv0);
    uint4 r;
    r.x = *(unsigned*)&p0; r.y = *(unsigned*)&p1;
    r.z = *(unsigned*)&p2; r.w = *(unsigned*)&p3;
    ((uint4*)out)[(long long)gid * LANES + lane] = r;
}

// ---------------- fp16 tensor-core GEMM (ldmatrix + cp.async pipeline) --------
__device__ __forceinline__ unsigned smem_u32(const void* p) {
    return (unsigned)__cvta_generic_to_shared(p);
}

__device__ __forceinline__ void cp16(unsigned dst, const void* src) {
    asm volatile("cp.async.cg.shared.global [%0], [%1], 16;" :: "r"(dst), "l"(src));
}

__device__ __forceinline__ void cp_commit() {
    asm volatile("cp.async.commit_group;");
}

template <int N>
__device__ __forceinline__ void cp_wait() {
    asm volatile("cp.async.wait_group %0;" :: "n"(N));
}

__device__ __forceinline__ void ldsm_x4(unsigned& r0, unsigned& r1, unsigned& r2, unsigned& r3,
                                        unsigned addr) {
    asm volatile("ldmatrix.sync.aligned.m8n8.x4.shared.b16 {%0,%1,%2,%3}, [%4];"
                 : "=r"(r0), "=r"(r1), "=r"(r2), "=r"(r3) : "r"(addr));
}

__device__ __forceinline__ void ldsm_x4_t(unsigned& r0, unsigned& r1, unsigned& r2, unsigned& r3,
                                          unsigned addr) {
    asm volatile("ldmatrix.sync.aligned.m8n8.x4.trans.shared.b16 {%0,%1,%2,%3}, [%4];"
                 : "=r"(r0), "=r"(r1), "=r"(r2), "=r"(r3) : "r"(addr));
}

__device__ __forceinline__ void mma_f16(float* c, const unsigned* a, const unsigned* b) {
    asm volatile(
        "mma.sync.aligned.m16n8k16.row.col.f32.f16.f16.f32 "
        "{%0,%1,%2,%3}, {%4,%5,%6,%7}, {%8,%9}, {%0,%1,%2,%3};"
        : "+f"(c[0]), "+f"(c[1]), "+f"(c[2]), "+f"(c[3])
        : "r"(a[0]), "r"(a[1]), "r"(a[2]), "r"(a[3]), "r"(b[0]), "r"(b[1]));
}

// C[N,M] = A[N,K] @ W[K,M]. Half in, fp32 accum. BM=128, BN=64, BK=32, 256 thr.
// 2-stage cp.async double buffering. SMAX: fused bias + row log_softmax to out.
template <int K, int M, bool BIAS_RELU, bool OUTH, bool SMAX>
__global__ void __launch_bounds__(256)
hgemm_kernel(const __half* __restrict__ A, const __half* __restrict__ W,
             const float* __restrict__ bias, void* __restrict__ Cv,
             float* __restrict__ out, int layer) {
    constexpr int NS = K / 32;                       // K-steps
    constexpr int A_ELEM = 128 * 40;                 // one A stage (halves)
    constexpr int B_ELEM = 32 * 72;                  // one B stage
    constexpr int PIPE_BYTES = 2 * (A_ELEM + B_ELEM) * 2;
    constexpr int PS_BYTES = 128 * 66 * 4;
    constexpr int SMEM_BYTES = (SMAX && PS_BYTES > PIPE_BYTES) ? PS_BYTES : PIPE_BYTES;
    __shared__ __align__(16) unsigned char smemraw[SMEM_BYTES];
    __half* Asb = reinterpret_cast<__half*>(smemraw);                       // 2 stages
    __half* Bsb = reinterpret_cast<__half*>(smemraw + 2 * A_ELEM * 2);      // 2 stages
    float  (*ps)[66] = reinterpret_cast<float(*)[66]>(smemraw);

    const int t = threadIdx.x;
    const int lane = t & 31;
    const int warp = t >> 5;
    const int wm = warp & 3;
    const int wn = warp >> 2;
    const int bm = blockIdx.x * 128;
    const int bn = blockIdx.y * 64;

    float acc[2][4][4];
#pragma unroll
    for (int mi = 0; mi < 2; mi++)
#pragma unroll
        for (int ni = 0; ni < 4; ni++)
#pragma unroll
            for (int r = 0; r < 4; r++) acc[mi][ni][r] = 0.0f;

    // per-thread staging coords
    const int arow0 = t >> 2,       ac4_0 = (t & 3) * 8;         // +64 rows for r=1
    const int brow  = t >> 3,       bc8   = (t & 7) * 8;

    auto stage = [&](int s, int buf) {
        __half* As = Asb + buf * A_ELEM;
        __half* Bs = Bsb + buf * B_ELEM;
        int k0 = s * 32;
#pragma unroll
        for (int r = 0; r < 2; r++) {
            int row = arow0 + r * 64;
            int grow = bm + row; if (grow > NN - 1) grow = NN - 1;   // clamp (masked at epilogue)
            cp16(smem_u32(&As[row * 40 + ac4_0]), &A[(long long)grow * K + k0 + ac4_0]);
        }
        cp16(smem_u32(&Bs[brow * 72 + bc8]), &W[(long long)(k0 + brow) * M + bn + bc8]);
    };

    stage(0, 0);
    cp_commit();

    for (int s = 0; s < NS; s++) {
        if (s + 1 < NS) {
            stage(s + 1, (s + 1) & 1);
            cp_commit();
            cp_wait<1>();
        } else {
            cp_wait<0>();
        }
        __syncthreads();
        const __half (*As)[40] = reinterpret_cast<const __half(*)[40]>(Asb + (s & 1) * A_ELEM);
        const __half (*Bs)[72] = reinterpret_cast<const __half(*)[72]>(Bsb + (s & 1) * B_ELEM);
#pragma unroll
        for (int ks = 0; ks < 2; ks++) {
            unsigned a[2][4], b[4][2];
#pragma unroll
            for (int mi = 0; mi < 2; mi++) {
                int row = wm * 32 + mi * 16 + (lane & 15);
                int col = ks * 16 + (lane >> 4) * 8;
                ldsm_x4(a[mi][0], a[mi][1], a[mi][2], a[mi][3], smem_u32(&As[row][col]));
            }
#pragma unroll
            for (int p = 0; p < 2; p++) {
                int row = ks * 16 + ((lane >> 3) & 1) * 8 + (lane & 7);
                int col = wn * 32 + p * 16 + (lane >> 4) * 8;
                ldsm_x4_t(b[2 * p][0], b[2 * p][1], b[2 * p + 1][0], b[2 * p + 1][1],
                          smem_u32(&Bs[row][col]));
            }
#pragma unroll
            for (int mi = 0; mi < 2; mi++)
#pragma unroll
                for (int ni = 0; ni < 4; ni++)
                    mma_f16(acc[mi][ni], a[mi], b[ni]);
        }
        __syncthreads();
    }

    if (SMAX) {
#pragma unroll
        for (int mi = 0; mi < 2; mi++)
#pragma unroll
            for (int ni = 0; ni < 4; ni++) {
                int col = wn * 32 + ni * 8 + 2 * (lane & 3);
#pragma unroll
                for (int h = 0; h < 2; h++) {
                    int row = wm * 32 + mi * 16 + (lane >> 2) + h * 8;
                    *(float2*)&ps[row][col] =
                        make_float2(acc[mi][ni][2 * h], acc[mi][ni][2 * h + 1]);
                }
            }
        __syncthreads();
        int gi = t >> 3, sub = t & 7;
#pragma unroll
        for (int pass = 0; pass < 4; pass++) {
            int r = pass * 32 + gi;
            int grow = bm + r;
            float v[5];
#pragma unroll
            for (int i = 0; i < 5; i++) v[i] = ps[r][sub + 8 * i] + bias[sub + 8 * i];
            float m = fmaxf(fmaxf(fmaxf(v[0], v[1]), fmaxf(v[2], v[3])), v[4]);
#pragma unroll
            for (int o = 1; o < 8; o <<= 1) m = fmaxf(m, __shfl_xor_sync(0xffffffffu, m, o));
            float s2 = 0.0f;
#pragma unroll
            for (int i = 0; i < 5; i++) s2 += expf(v[i] - m);
#pragma unroll
            for (int o = 1; o < 8; o <<= 1) s2 += __shfl_xor_sync(0xffffffffu, s2, o);
            float lse = m + logf(s2);
            if (grow < NN) {
                float* op = out + (long long)grow * 160 + layer * 40;
#pragma unroll
                for (int i = 0; i < 5; i++) op[sub + 8 * i] = v[i] - lse;
            }
        }
    } else {
#pragma unroll
        for (int mi = 0; mi < 2; mi++) {
#pragma unroll
            for (int ni = 0; ni < 4; ni++) {
                int col = bn + wn * 32 + ni * 8 + 2 * (lane & 3);
                float bv0 = 0.f, bv1 = 0.f;
                if (BIAS_RELU) { bv0 = bias[col]; bv1 = bias[col + 1]; }
#pragma unroll
                for (int h = 0; h < 2; h++) {
                    int row = bm + wm * 32 + mi * 16 + (lane >> 2) + h * 8;
                    if (row < NN) {
                        float v0 = acc[mi][ni][2 * h];
                        float v1 = acc[mi][ni][2 * h + 1];
                        if (BIAS_RELU) {
                            v0 = fmaxf(v0 + bv0, 0.0f);
                            v1 = fmaxf(v1 + bv1, 0.0f);
                        }
                        if (OUTH) {
                            __half2 p = __floats2half2_rn(v0, v1);
                            *(__half2*)&((__half*)Cv)[(long long)row * M + col] = p;
                        } else {
                            *(float2*)&((float*)Cv)[(long long)row * M + col] = make_float2(v0, v1);
                        }
                    }
                }
            }
        }
    }
}

// ---------------- last layer: half 40-dim aggregate + bias + log_softmax ------
__global__ void agg40h_kernel(const __half* __restrict__ P, const float* __restrict__ bias,
                              float* __restrict__ out) {
    int gid = blockIdx.x * (blockDim.x >> 3) + (threadIdx.x >> 3);
    int t = threadIdx.x & 7;
    bool valid = gid < NN;
    bool cvalid = t < 5;
    float v[8];
#pragma unroll
    for (int i = 0; i < 8; i++) v[i] = 0.0f;
    const uint4* Pv = (const uint4*)P;
    int beg = 0, end = 0;
    float dinv0 = 0.0f;
    if (valid) {
        dinv0 = g_dinv[gid];
        uint4 u = Pv[gid * 8 + t];
        acc_u4(v, u, dinv0);
        beg = g_rowptr[gid];
        end = g_rowptr[gid + 1];
    }
    int j = beg;
    for (; j + 3 < end; j += 4) {
        int s0 = g_csr[j],     s1 = g_csr[j + 1];
        int s2 = g_csr[j + 2], s3 = g_csr[j + 3];
        float c0 = __ldg(&g_dinv[s0]);
        float c1 = __ldg(&g_dinv[s1]);
        float c2 = __ldg(&g_dinv[s2]);
        float c3 = __ldg(&g_dinv[s3]);
        uint4 u0 = __ldg(&Pv[s0 * 8 + t]);
        uint4 u1 = __ldg(&Pv[s1 * 8 + t]);
        uint4 u2 = __ldg(&Pv[s2 * 8 + t]);
        uint4 u3 = __ldg(&Pv[s3 * 8 + t]);
        acc_u4(v, u0, c0);
        acc_u4(v, u1, c1);
        acc_u4(v, u2, c2);
        acc_u4(v, u3, c3);
    }
    for (; j < end; j++) {
        int s = g_csr[j];
        float c = __ldg(&g_dinv[s]);
        uint4 u = __ldg(&Pv[s * 8 + t]);
        acc_u4(v, u, c);
    }
    float m = -1e30f;
    if (cvalid) {
#pragma unroll
        for (int i = 0; i < 8; i++) {
            v[i] = v[i] * dinv0 + bias[8 * t + i];
            m = fmaxf(m, v[i]);
        }
    }
#pragma unroll
    for (int o = 1; o < 8; o <<= 1) m = fmaxf(m, __shfl_xor_sync(0xffffffffu, m, o));
    float s = 0.0f;
    if (cvalid) {
#pragma unroll
        for (int i = 0; i < 8; i++) s += expf(v[i] - m);
    }
#pragma unroll
    for (int o = 1; o < 8; o <<= 1) s += __shfl_xor_sync(0xffffffffu, s, o);
    float lse = m + logf(s);
    if (valid && cvalid) {
        float* op = out + (long long)gid * 160 + 120 + 8 * t;
        *(float4*)&op[0] = make_float4(v[0] - lse, v[1] - lse, v[2] - lse, v[3] - lse);
        *(float4*)&op[4] = make_float4(v[4] - lse, v[5] - lse, v[6] - lse, v[7] - lse);
    }
}

// ---------------- launch -------------------------------------------------------
extern "C" void kernel_launch(void* const* d_in, const int* in_sizes, int n_in,
                              void* d_out, int out_size) {
    const float* x   = (const float*)d_in[0];
    const void*  ei  = d_in[1];
    const float* Wc0 = (const float*)d_in[2];
    const float* bc0 = (const float*)d_in[3];
    const float* Wc1 = (const float*)d_in[4];
    const float* bc1 = (const float*)d_in[5];
    // d_in[6], d_in[7] (Wc2, bc2): dead — final Wc output is never used
    const float* We0 = (const float*)d_in[8];
    const float* be0 = (const float*)d_in[9];
    const float* We1 = (const float*)d_in[10];
    const float* be1 = (const float*)d_in[11];
    const float* We2 = (const float*)d_in[12];
    const float* be2 = (const float*)d_in[13];
    const float* We3 = (const float*)d_in[14];
    const float* be3 = (const float*)d_in[15];
    float* out = (float*)d_out;
    int E = in_sizes[1] / 2;

    __half *xh, *h1h, *h2h, *h2ah, *h3h, *p64h, *wph, *wc0h, *wc1h;
    cudaGetSymbolAddress((void**)&xh,   g_xh);
    cudaGetSymbolAddress((void**)&h1h,  g_h1h);
    cudaGetSymbolAddress((void**)&h2h,  g_h2h);
    cudaGetSymbolAddress((void**)&h2ah, g_h2ah);
    cudaGetSymbolAddress((void**)&h3h,  g_h3h);
    cudaGetSymbolAddress((void**)&p64h, g_p64h);
    cudaGetSymbolAddress((void**)&wph,  g_Wph);
    cudaGetSymbolAddress((void**)&wc0h, g_Wc0h);
    cudaGetSymbolAddress((void**)&wc1h, g_Wc1h);
    __half* wp0 = wph;
    __half* wp1 = wph + 1 * 256 * 64;
    __half* wp2 = wph + 2 * 256 * 64;
    __half* wp3 = wph + 3 * 256 * 64;

    static cudaStream_t s1 = nullptr;
    static cudaEvent_t evStart, evPre, evA1, evA2, evS1;
    if (!s1) {
        cudaStreamCreateWithFlags(&s1, cudaStreamNonBlocking);
        cudaEventCreateWithFlags(&evStart, cudaEventDisableTiming);
        cudaEventCreateWithFlags(&evPre,   cudaEventDisableTiming);
        cudaEventCreateWithFlags(&evA1,    cudaEventDisableTiming);
        cudaEventCreateWithFlags(&evA2,    cudaEventDisableTiming);
        cudaEventCreateWithFlags(&evS1,    cudaEventDisableTiming);
    }

    int nb = (NN + 1023) / 1024;
    dim3 g1((NN + 127) / 128, 1);
    dim3 g4((NN + 127) / 128, 4);
    int  gs = (NN + 31) / 32;

    cudaEventRecord(evStart, 0);
    cudaStreamWaitEvent(s1, evStart, 0);

    // s1: all weight/feature prep in ONE kernel, then fused layer-0 projection
    prep_all_kernel<<<12788, 256, 0, s1>>>(x, Wc0, Wc1, We0, We1, We2, We3);
    cudaEventRecord(evPre, s1);
    hgemm_kernel<128, 64, false, false, true><<<g1, 256, 0, s1>>>(xh, wp0, be0, nullptr, out, 0);

    // main: CSR preprocessing (overlaps s1)
    init_kernel<<<(NN + 255) / 256, 256>>>((const int*)ei);
    count_kernel<<<(E + 255) / 256, 256>>>(ei, E);
    scan1_kernel<<<nb, 1024>>>();
    scan23_kernel<<<(NN + 255) / 256, 256>>>(nb);
    fill_kernel<<<(E + 255) / 256, 256>>>(ei, E);

    // main chain
    cudaStreamWaitEvent(0, evPre, 0);
    agg_u4_kernel<16><<<(NN * 16 + 255) / 256, 256>>>(xh, h1h);     // D=128
    cudaEventRecord(evA1, 0);
    hgemm_kernel<128, 256, true, true, false><<<g4, 256>>>(h1h, wc0h, bc0, h2h, nullptr, 0);
    agg_u4_kernel<32><<<(NN * 32 + 255) / 256, 256>>>(h2h, h2ah);   // D=256
    cudaEventRecord(evA2, 0);
    hgemm_kernel<256, 256, true, true, false><<<g4, 256>>>(h2ah, wc1h, bc1, h3h, nullptr, 0);
    hgemm_kernel<256, 64, false, true, false><<<g1, 256>>>(h3h, wp3, nullptr, p64h, nullptr, 0);
    agg40h_kernel<<<gs, 256>>>(p64h, be3, out);

    // s1: fused projection layers 1/2 overlap the Wc GEMMs / aggs
    cudaStreamWaitEvent(s1, evA1, 0);
    hgemm_kernel<128, 64, false, false, true><<<g1, 256, 0, s1>>>(h1h, wp1, be1, nullptr, out, 1);
    cudaStreamWaitEvent(s1, evA2, 0);
    hgemm_kernel<256, 64, false, false, true><<<g1, 256, 0, s1>>>(h2ah, wp2, be2, nullptr, out, 2);
    cudaEventRecord(evS1, s1);

    cudaStreamWaitEvent(0, evS1, 0);
}